// round 10
// baseline (speedup 1.0000x reference)
#include <cuda_runtime.h>
#include <cuda_bf16.h>
#include <math.h>
#include <stdint.h>

// ---------------------------------------------------------------------------
// Problem constants
// ---------------------------------------------------------------------------
#define BB     8192
#define NPOS   49
#define MCONV  (BB*NPOS)        // 401408
#define CI1    96
#define CO1    64
#define K1     (9*CI1)          // 864
#define CI2    64
#define CO2    128
#define K2     (9*CI2)          // 576
#define FUSED  6368
#define HH     512
#define G3H    1536
#define KS     40               // smem k-stride in bf16 (80B rows -> conflict-free)

typedef __nv_bfloat16 bf;

// ---------------------------------------------------------------------------
// Scratch (__device__ globals). Compact activation buffers (no spatial pad);
// SAME padding handled by predicated zero-fill cp.async in conv loaders.
// ---------------------------------------------------------------------------
__device__ __align__(16) bf    g_x    [BB*NPOS*CI1];   // [B][49][96]
__device__ __align__(16) bf    g_y1   [BB*NPOS*CI2];   // [B][49][64]
__device__ __align__(16) bf    g_fused[BB*FUSED];
__device__ __align__(16) bf    g_W1re [CO1*K1];
__device__ __align__(16) bf    g_W2re [CO2*K2];
__device__ __align__(16) bf    g_preW [HH*FUSED];
__device__ __align__(16) bf    g_Wih  [4*G3H*HH];
__device__ __align__(16) bf    g_Wa   [8*HH*HH];
__device__ __align__(16) bf    g_lat  [BB*HH];
__device__ __align__(16) float g_gx   [BB*G3H];
__device__ __align__(16) bf    g_lat2 [BB*HH];
__device__ __align__(16) float g_lat3 [BB*HH];
__device__ int g_perm[BB], g_rowTask[BB];
__device__ int g_counts[8], g_cursor[8], g_off[9];
__device__ int g_tileG [80], g_tileM0 [80], g_tileE [80], g_nGru[1];
__device__ int g_tileT [80], g_tileM0a[80], g_tileEa[80], g_nAd[1];

// ---------------------------------------------------------------------------
// Helpers
// ---------------------------------------------------------------------------
__device__ __forceinline__ uint32_t pack_bf2(float lo, float hi) {
    __nv_bfloat162 p = __floats2bfloat162_rn(lo, hi);
    return *reinterpret_cast<uint32_t*>(&p);
}
__device__ __forceinline__ void cpa16(uint32_t dst, const void* src) {
    asm volatile("cp.async.cg.shared.global [%0], [%1], 16;\n"
                 :: "r"(dst), "l"(src));
}
__device__ __forceinline__ void cpa16p(uint32_t dst, const void* src, int sz) {
    asm volatile("cp.async.cg.shared.global [%0], [%1], 16, %2;\n"
                 :: "r"(dst), "l"(src), "r"(sz));
}
#define CP_COMMIT() asm volatile("cp.async.commit_group;\n" ::: "memory")
#define CP_WAIT0()  asm volatile("cp.async.wait_group 0;\n" ::: "memory")
#define CP_WAIT1()  asm volatile("cp.async.wait_group 1;\n" ::: "memory")

__device__ __forceinline__ void mma_bf16(float4& d,
    uint32_t a0, uint32_t a1, uint32_t a2, uint32_t a3,
    uint32_t b0, uint32_t b1)
{
    asm volatile(
        "mma.sync.aligned.m16n8k16.row.col.f32.bf16.bf16.f32 "
        "{%0,%1,%2,%3}, {%4,%5,%6,%7}, {%8,%9}, {%0,%1,%2,%3};\n"
        : "+f"(d.x), "+f"(d.y), "+f"(d.z), "+f"(d.w)
        : "r"(a0), "r"(a1), "r"(a2), "r"(a3), "r"(b0), "r"(b1));
}
__device__ __forceinline__ void ldm_x4(uint32_t (&r)[4], uint32_t addr) {
    asm volatile("ldmatrix.sync.aligned.m8n8.x4.shared.b16 {%0,%1,%2,%3}, [%4];"
                 : "=r"(r[0]), "=r"(r[1]), "=r"(r[2]), "=r"(r[3]) : "r"(addr));
}

// One k32 tile of MMAs over MF*16 x NF*8 warp tile, ldmatrix fragment loads.
template<int MF, int NF>
__device__ __forceinline__ void tile_mma_ldm(
    uint32_t sA, uint32_t sB, int mBase, int nBase, int lane,
    float4 (&acc)[MF][NF])
{
    int la = lane & 15, ka = lane >> 4;                 // A: row-in-16, k-half
    int nb = (lane & 7) + ((lane >> 4) << 3);           // B: n-row
    int kb = (lane >> 3) & 1;                           // B: k-half
#pragma unroll
    for (int ks = 0; ks < 2; ks++) {
        uint32_t b[NF][2];
#pragma unroll
        for (int p = 0; p < NF/2; p++) {
            uint32_t r[4];
            ldm_x4(r, sB + ((nBase + p*16 + nb)*KS + ks*16 + kb*8)*2);
            b[2*p  ][0] = r[0]; b[2*p  ][1] = r[1];
            b[2*p+1][0] = r[2]; b[2*p+1][1] = r[3];
        }
#pragma unroll
        for (int mf = 0; mf < MF; mf++) {
            uint32_t a[4];
            ldm_x4(a, sA + ((mBase + mf*16 + la)*KS + ks*16 + ka*8)*2);
#pragma unroll
            for (int nf = 0; nf < NF; nf++)
                mma_bf16(acc[mf][nf], a[0], a[1], a[2], a[3],
                         b[nf][0], b[nf][1]);
        }
    }
}

// ---------------------------------------------------------------------------
// Weight re-layout / conversion kernels
// ---------------------------------------------------------------------------
__global__ void reorder_w1_k(const float* __restrict__ w) {
    int idx = blockIdx.x * blockDim.x + threadIdx.x;
    int n = idx / K1, k = idx % K1;
    int t = k / CI1, i = k % CI1;
    g_W1re[idx] = __float2bfloat16(w[(n*CI1 + i)*9 + t]);
}
__global__ void reorder_w2_k(const float* __restrict__ w) {
    int idx = blockIdx.x * blockDim.x + threadIdx.x;
    int n = idx / K2, k = idx % K2;
    int t = k / CI2, i = k % CI2;
    g_W2re[idx] = __float2bfloat16(w[(n*CI2 + i)*9 + t]);
}
// one block per output row n: stage the row in smem, both sides coalesced
__global__ __launch_bounds__(256) void reorder_pre_k(const float* __restrict__ w) {
    __shared__ float buf[FUSED];
    int n = blockIdx.x;
    for (int k = threadIdx.x; k < FUSED; k += 256) buf[k] = w[n*FUSED + k];
    __syncthreads();
    for (int k = threadIdx.x; k < FUSED; k += 256) {
        int src;
        if (k < 6272) { int pos = k >> 7, ch = k & 127; src = ch*49 + pos; }
        else src = k;
        g_preW[n*FUSED + k] = __float2bfloat16(buf[src]);
    }
}
__global__ void cvt4_k(const float* __restrict__ src, bf* __restrict__ dst, int n4) {
    int i = blockIdx.x * blockDim.x + threadIdx.x;
    if (i >= n4) return;
    float4 v = *(const float4*)(src + i*4);
    uint2 o; o.x = pack_bf2(v.x, v.y); o.y = pack_bf2(v.z, v.w);
    *(uint2*)(dst + i*4) = o;
}

// ---------------------------------------------------------------------------
// Embedding gather -> compact activation [B][49][96] bf16 (16B stores)
// ---------------------------------------------------------------------------
__global__ void embed_k(const int* __restrict__ obj, const int* __restrict__ col,
                        const int* __restrict__ sta,
                        const float* __restrict__ eo, const float* __restrict__ ec,
                        const float* __restrict__ es) {
    long idx = (long)blockIdx.x * blockDim.x + threadIdx.x;   // MCONV*12
    int sub = (int)(idx % 12);
    long cell = idx / 12;
    int tbl = sub >> 2, j = sub & 3;
    int e; const float* tab;
    if (tbl == 0)      { e = obj[cell]; tab = eo; }
    else if (tbl == 1) { e = col[cell]; tab = ec; }
    else               { e = sta[cell]; tab = es; }
    float4 v0 = *(const float4*)(tab + e*32 + j*8);
    float4 v1 = *(const float4*)(tab + e*32 + j*8 + 4);
    uint4 o;
    o.x = pack_bf2(v0.x, v0.y); o.y = pack_bf2(v0.z, v0.w);
    o.z = pack_bf2(v1.x, v1.y); o.w = pack_bf2(v1.z, v1.w);
    *(uint4*)(g_x + cell*CI1 + tbl*32 + j*8) = o;
}

__global__ void tail_k(const int* __restrict__ dir, const int* __restrict__ task,
                       const float* __restrict__ ed, const float* __restrict__ et) {
    int idx = blockIdx.x * blockDim.x + threadIdx.x;          // BB*24
    int b = idx / 24, sub = idx % 24;
    float4 v; int dst;
    if (sub < 8) { v = *(const float4*)(ed + dir[b]*32 + sub*4);  dst = 6272 + sub*4; }
    else { int j = sub - 8; v = *(const float4*)(et + task[b]*64 + j*4); dst = 6304 + j*4; }
    uint2 o; o.x = pack_bf2(v.x, v.y); o.y = pack_bf2(v.z, v.w);
    *(uint2*)(g_fused + (long)b*FUSED + dst) = o;
}

// ---------------------------------------------------------------------------
// conv1: implicit GEMM  M=401408, N=64, K=864 -> relu -> compact y1
// A read from compact g_x with predicated taps (zero-fill out-of-grid).
// CTA 128x64, 8 warps (4x2), warp tile 32x32; 3-stage cp.async, 1 sync/tile
// ---------------------------------------------------------------------------
__global__ __launch_bounds__(256) void conv1_k(const float* __restrict__ bias) {
    extern __shared__ __align__(16) bf smem1[];
    const int stageE = (128 + 64)*KS;
    int m0 = blockIdx.x * 128;
    int tid = threadIdx.x;
    int warp = tid >> 5, lane = tid & 31;
    int lq = lane >> 2, lr = lane & 3;
    int mBase = (warp >> 1) * 32, nBase = (warp & 1) * 32;
    uint32_t sbase = (uint32_t)__cvta_generic_to_shared(smem1);

    // per-thread load geometry: A rows rowA, rowA+64; W row rowA; chunk kc
    int rowA = tid >> 2, kc = tid & 3;
    int bA[2], rA[2], cA[2];
#pragma unroll
    for (int h = 0; h < 2; h++) {
        int m = m0 + rowA + h*64;
        bA[h] = m / 49;
        int pos = m % 49;
        rA[h] = pos / 7; cA[h] = pos % 7;
    }

    float4 acc[2][4];
#pragma unroll
    for (int i = 0; i < 2; i++)
#pragma unroll
        for (int j = 0; j < 4; j++) acc[i][j] = make_float4(0.f,0.f,0.f,0.f);

    const int KT = K1/32;                       // 27
    auto load_tile = [&](int kt, int buf) {
        int k0 = kt*32;
        int tap = k0 / CI1;                     // 0..8 (constant within tile)
        int i0  = k0 - tap*CI1;                 // 0, 32, 64
        int dr = tap/3 - 1, dc = tap%3 - 1;
        uint32_t sb = sbase + buf*stageE*2;
#pragma unroll
        for (int h = 0; h < 2; h++) {
            int nr = rA[h] + dr, nc = cA[h] + dc;
            int sz = ((unsigned)nr < 7u && (unsigned)nc < 7u) ? 16 : 0;
            const bf* src = g_x + ((long)bA[h]*49 + nr*7 + nc)*CI1 + i0 + kc*8;
            cpa16p(sb + ((rowA + h*64)*KS + kc*8)*2, src, sz);
        }
        cpa16(sb + (128*KS + rowA*KS + kc*8)*2, g_W1re + rowA*K1 + k0 + kc*8);
        CP_COMMIT();
    };

    load_tile(0, 0); load_tile(1, 1);
    for (int kt = 0; kt < KT; kt++) {
        if (kt + 1 < KT) { CP_WAIT1(); } else { CP_WAIT0(); }
        __syncthreads();
        if (kt + 2 < KT) load_tile(kt + 2, (kt + 2) % 3);
        uint32_t sA = sbase + (kt % 3)*stageE*2;
        tile_mma_ldm<2,4>(sA, sA + 128*KS*2, mBase, nBase, lane, acc);
    }

#pragma unroll
    for (int mf = 0; mf < 2; mf++) {
#pragma unroll
        for (int half = 0; half < 2; half++) {
            int m = m0 + mBase + mf*16 + lq + half*8;
            bf* dst = g_y1 + (long)m * CI2;
#pragma unroll
            for (int nf = 0; nf < 4; nf++) {
                int n = nBase + nf*8 + lr*2;
                float x0 = (half ? acc[mf][nf].z : acc[mf][nf].x) + bias[n];
                float x1 = (half ? acc[mf][nf].w : acc[mf][nf].y) + bias[n+1];
                *(uint32_t*)(dst + n) = pack_bf2(fmaxf(x0,0.f), fmaxf(x1,0.f));
            }
        }
    }
}

// ---------------------------------------------------------------------------
// conv2: implicit GEMM  M=401408, N=128, K=576 -> relu -> fused[pos*128+ch]
// A read from compact g_y1 with predicated taps.
// CTA 128x128, 8 warps (2x4), warp tile 64x32; 3-stage, 1 sync/tile
// ---------------------------------------------------------------------------
__global__ __launch_bounds__(256) void conv2_k(const float* __restrict__ bias) {
    extern __shared__ __align__(16) bf smem2[];
    const int stageE = (128 + 128)*KS;
    int m0 = blockIdx.x * 128;
    int tid = threadIdx.x;
    int warp = tid >> 5, lane = tid & 31;
    int lq = lane >> 2, lr = lane & 3;
    int mBase = (warp >> 2) * 64, nBase = (warp & 3) * 32;
    uint32_t sbase = (uint32_t)__cvta_generic_to_shared(smem2);

    int rowA = tid >> 2, kc = tid & 3;
    int bA[2], rA[2], cA[2];
#pragma unroll
    for (int h = 0; h < 2; h++) {
        int m = m0 + rowA + h*64;
        bA[h] = m / 49;
        int pos = m % 49;
        rA[h] = pos / 7; cA[h] = pos % 7;
    }

    float4 acc[4][4];
#pragma unroll
    for (int i = 0; i < 4; i++)
#pragma unroll
        for (int j = 0; j < 4; j++) acc[i][j] = make_float4(0.f,0.f,0.f,0.f);

    const int KT = K2/32;                       // 18
    auto load_tile = [&](int kt, int buf) {
        int k0 = kt*32;
        int tap = k0 / CI2;
        int i0  = k0 - tap*CI2;
        int dr = tap/3 - 1, dc = tap%3 - 1;
        uint32_t sb = sbase + buf*stageE*2;
#pragma unroll
        for (int h = 0; h < 2; h++) {
            int nr = rA[h] + dr, nc = cA[h] + dc;
            int sz = ((unsigned)nr < 7u && (unsigned)nc < 7u) ? 16 : 0;
            const bf* src = g_y1 + ((long)bA[h]*49 + nr*7 + nc)*CI2 + i0 + kc*8;
            cpa16p(sb + ((rowA + h*64)*KS + kc*8)*2, src, sz);
        }
#pragma unroll
        for (int h = 0; h < 2; h++) {
            int nrow = rowA + h*64;
            cpa16(sb + (128*KS + nrow*KS + kc*8)*2, g_W2re + nrow*K2 + k0 + kc*8);
        }
        CP_COMMIT();
    };

    load_tile(0, 0); load_tile(1, 1);
    for (int kt = 0; kt < KT; kt++) {
        if (kt + 1 < KT) { CP_WAIT1(); } else { CP_WAIT0(); }
        __syncthreads();
        if (kt + 2 < KT) load_tile(kt + 2, (kt + 2) % 3);
        uint32_t sA = sbase + (kt % 3)*stageE*2;
        tile_mma_ldm<4,4>(sA, sA + 128*KS*2, mBase, nBase, lane, acc);
    }

#pragma unroll
    for (int mf = 0; mf < 4; mf++) {
#pragma unroll
        for (int half = 0; half < 2; half++) {
            int m = m0 + mBase + mf*16 + lq + half*8;
            int b = m/49, pos = m%49;
            bf* dst = g_fused + (long)b*FUSED + pos*128;
#pragma unroll
            for (int nf = 0; nf < 4; nf++) {
                int n = nBase + nf*8 + lr*2;
                float x0 = (half ? acc[mf][nf].z : acc[mf][nf].x) + bias[n];
                float x1 = (half ? acc[mf][nf].w : acc[mf][nf].y) + bias[n+1];
                *(uint32_t*)(dst + n) = pack_bf2(fmaxf(x0,0.f), fmaxf(x1,0.f));
            }
        }
    }
}

// ---------------------------------------------------------------------------
// Generic TN GEMM (bf16 MMA, 3-stage cp.async, ldmatrix):
// C[m,n] = act( sum_k A[m,k]*W[n,k] + bias[n] ); optional perm gather,
// grouped M-tiles; output f32 (Cf) or bf16 (Cb).  CTA 128x128.
// ---------------------------------------------------------------------------
__global__ __launch_bounds__(256) void gemm_bf(
    const bf* __restrict__ A, int lda,
    const int* __restrict__ perm,
    const bf* __restrict__ Wg, long long wStride,
    const float* __restrict__ biasg, int biasStride,
    float* __restrict__ Cf, bf* __restrict__ Cb, int ldc,
    int K, int relu, int denseM,
    const int* __restrict__ tileG, const int* __restrict__ tileM0,
    const int* __restrict__ tileE, const int* __restrict__ nTilesPtr)
{
    extern __shared__ __align__(16) bf smemg[];
    const int stageE = (128 + 128)*KS;
    int m0, mEnd, g;
    if (tileG) {
        int t = blockIdx.x;
        if (t >= *nTilesPtr) return;
        g = tileG[t]; m0 = tileM0[t]; mEnd = tileE[t];
    } else {
        g = 0; m0 = blockIdx.x * 128; mEnd = denseM;
    }
    const bf* W = Wg + (long long)g * wStride;
    const float* bias = biasg + g * biasStride;
    int n0 = blockIdx.y * 128;

    int tid = threadIdx.x;
    int warp = tid >> 5, lane = tid & 31;
    int lq = lane >> 2, lr = lane & 3;
    int mBase = (warp >> 2) * 64, nBase = (warp & 3) * 32;
    uint32_t sbase = (uint32_t)__cvta_generic_to_shared(smemg);

    float4 acc[4][4];
#pragma unroll
    for (int i = 0; i < 4; i++)
#pragma unroll
        for (int j = 0; j < 4; j++) acc[i][j] = make_float4(0.f,0.f,0.f,0.f);

    const int KT = K/32;
    auto load_tile = [&](int kt, int buf) {
        int k0 = kt*32;
        uint32_t sb = sbase + buf*stageE*2;
#pragma unroll
        for (int it = 0; it < 4; it++) {
            int c = tid + it*256;
            const bf* src; uint32_t dst; int sz = 16;
            if (c < 512) {
                int row = c >> 2, kc = c & 3;
                int m = m0 + row;
                long ar = 0;
                if (m < mEnd) ar = perm ? perm[m] : m; else sz = 0;
                src = A + ar*lda + k0 + kc*8;
                dst = sb + (row*KS + kc*8)*2;
            } else {
                int row = (c - 512) >> 2, kc = c & 3;
                src = W + (long)(n0 + row)*K + k0 + kc*8;
                dst = sb + (128*KS + row*KS + kc*8)*2;
            }
            cpa16p(dst, src, sz);
        }
        CP_COMMIT();
    };

    load_tile(0, 0); load_tile(1, 1);
    for (int kt = 0; kt < KT; kt++) {
        if (kt + 1 < KT) { CP_WAIT1(); } else { CP_WAIT0(); }
        __syncthreads();
        if (kt + 2 < KT) load_tile(kt + 2, (kt + 2) % 3);
        uint32_t sA = sbase + (kt % 3)*stageE*2;
        tile_mma_ldm<4,4>(sA, sA + 128*KS*2, mBase, nBase, lane, acc);
    }

#pragma unroll
    for (int mf = 0; mf < 4; mf++) {
#pragma unroll
        for (int half = 0; half < 2; half++) {
            int m = m0 + mBase + mf*16 + lq + half*8;
            if (m >= mEnd) continue;
#pragma unroll
            for (int nf = 0; nf < 4; nf++) {
                int n = n0 + nBase + nf*8 + lr*2;
                float x0 = (half ? acc[mf][nf].z : acc[mf][nf].x) + bias[n];
                float x1 = (half ? acc[mf][nf].w : acc[mf][nf].y) + bias[n+1];
                if (relu) { x0 = fmaxf(x0, 0.f); x1 = fmaxf(x1, 0.f); }
                if (Cb) {
                    *(uint32_t*)(Cb + (long)m*ldc + n) = pack_bf2(x0, x1);
                } else {
                    float2 v; v.x = x0; v.y = x1;
                    *(float2*)(Cf + (long)m*ldc + n) = v;
                }
            }
        }
    }
}

// ---------------------------------------------------------------------------
// Task sort / compaction
// ---------------------------------------------------------------------------
__global__ void sort_zero_k() {
    int t = threadIdx.x;
    if (t < 8) { g_counts[t] = 0; g_cursor[t] = 0; }
}
__global__ void sort_count_k(const int* __restrict__ task) {
    int b = blockIdx.x * blockDim.x + threadIdx.x;
    if (b < BB) atomicAdd(&g_counts[task[b]], 1);
}
__global__ void sort_off_k() {
    if (threadIdx.x == 0 && blockIdx.x == 0) {
        int off = 0;
        for (int t = 0; t < 8; t++) { g_off[t] = off; off += g_counts[t]; }
        g_off[8] = off;
        int idx = 0;
        for (int g = 0; g < 4; g++) {
            int s = g_off[g];
            int e = (g < 3) ? g_off[g+1] : BB;
            for (int m0 = s; m0 < e; m0 += 128) {
                g_tileG[idx] = g; g_tileM0[idx] = m0; g_tileE[idx] = e; idx++;
            }
        }
        g_nGru[0] = idx;
        idx = 0;
        for (int t = 0; t < 8; t++) {
            int s = g_off[t], e = g_off[t+1];
            for (int m0 = s; m0 < e; m0 += 128) {
                g_tileT[idx] = t; g_tileM0a[idx] = m0; g_tileEa[idx] = e; idx++;
            }
        }
        g_nAd[0] = idx;
    }
}
__global__ void sort_scatter_k(const int* __restrict__ task) {
    int b = blockIdx.x * blockDim.x + threadIdx.x;
    if (b < BB) {
        int t = task[b];
        int p = g_off[t] + atomicAdd(&g_cursor[t], 1);
        g_perm[p] = b;
        g_rowTask[p] = t;
    }
}

// ---------------------------------------------------------------------------
// GRU elementwise (h0 = 0):  lat2 = (1 - z) * tanh(nx + r*nh)
// ---------------------------------------------------------------------------
__global__ void gru_elem_k(const float* __restrict__ b_hh) {
    int p = blockIdx.x, h = threadIdx.x;
    int t = g_rowTask[p];
    int g = (t < 3) ? t : 3;
    const float* gxr = g_gx + (long)p*G3H;
    const float* bh  = b_hh + g*G3H;
    float r = 1.f / (1.f + expf(-(gxr[h]        + bh[h])));
    float z = 1.f / (1.f + expf(-(gxr[512 + h]  + bh[512 + h])));
    float n = tanhf(gxr[1024 + h] + r * bh[1024 + h]);
    g_lat2[(long)p*HH + h] = __float2bfloat16((1.f - z) * n);
}

// ---------------------------------------------------------------------------
// Heads: 7 logits + value per sample, scattered to original order
// ---------------------------------------------------------------------------
__global__ void heads_k(const float* __restrict__ Wh, const float* __restrict__ bh2,
                        const float* __restrict__ vw, const float* __restrict__ vb,
                        float* __restrict__ out) {
    int p = blockIdx.x * 8 + (threadIdx.x >> 5);
    int lane = threadIdx.x & 31;
    if (p >= BB) return;
    int t = g_rowTask[p];
    int borig = g_perm[p];
    const float* lrow = g_lat3 + (long)p*HH;
    const float* wt = Wh + t*7*HH;
    float acc[8];
#pragma unroll
    for (int a = 0; a < 8; a++) acc[a] = 0.f;
    for (int h = lane; h < HH; h += 32) {
        float x = lrow[h];
#pragma unroll
        for (int a = 0; a < 7; a++) acc[a] += x * wt[a*HH + h];
        acc[7] += x * vw[h];
    }
#pragma unroll
    for (int a = 0; a < 8; a++)
#pragma unroll
        for (int off = 16; off; off >>= 1)
            acc[a] += __shfl_down_sync(0xffffffff, acc[a], off);
    if (lane == 0) {
#pragma unroll
        for (int a = 0; a < 7; a++) out[borig*7 + a] = acc[a] + bh2[t*7 + a];
        out[BB*7 + borig] = acc[7] + vb[0];
    }
}

// ---------------------------------------------------------------------------
// Launch
// ---------------------------------------------------------------------------
extern "C" void kernel_launch(void* const* d_in, const int* in_sizes, int n_in,
                              void* d_out, int out_size) {
    const int*   obj   = (const int*)  d_in[0];
    const int*   color = (const int*)  d_in[1];
    const int*   state = (const int*)  d_in[2];
    const int*   dir   = (const int*)  d_in[3];
    const int*   task  = (const int*)  d_in[4];
    const float* eo    = (const float*)d_in[5];
    const float* ec    = (const float*)d_in[6];
    const float* es    = (const float*)d_in[7];
    const float* ed    = (const float*)d_in[8];
    const float* et    = (const float*)d_in[9];
    const float* c1w   = (const float*)d_in[10];
    const float* c1b   = (const float*)d_in[11];
    const float* c2w   = (const float*)d_in[12];
    const float* c2b   = (const float*)d_in[13];
    const float* prew  = (const float*)d_in[14];
    const float* preb  = (const float*)d_in[15];
    const float* W_ih  = (const float*)d_in[16];
    const float* b_ih  = (const float*)d_in[18];
    const float* b_hh  = (const float*)d_in[19];
    const float* Wa    = (const float*)d_in[20];
    const float* ba    = (const float*)d_in[21];
    const float* Wh    = (const float*)d_in[22];
    const float* bh2   = (const float*)d_in[23];
    const float* vw    = (const float*)d_in[24];
    const float* vb    = (const float*)d_in[25];
    float* out = (float*)d_out;

    bf *p_fused, *p_preW, *p_lat, *p_lat2, *p_Wih, *p_Wa;
    float *p_gx, *p_lat3;
    int *p_perm, *p_tG, *p_tM0, *p_tE, *p_nG, *p_tT, *p_tM0a, *p_tEa, *p_nA;
    cudaGetSymbolAddress((void**)&p_fused, g_fused);
    cudaGetSymbolAddress((void**)&p_preW,  g_preW);
    cudaGetSymbolAddress((void**)&p_lat,   g_lat);
    cudaGetSymbolAddress((void**)&p_gx,    g_gx);
    cudaGetSymbolAddress((void**)&p_lat2,  g_lat2);
    cudaGetSymbolAddress((void**)&p_lat3,  g_lat3);
    cudaGetSymbolAddress((void**)&p_Wih,   g_Wih);
    cudaGetSymbolAddress((void**)&p_Wa,    g_Wa);
    cudaGetSymbolAddress((void**)&p_perm,  g_perm);
    cudaGetSymbolAddress((void**)&p_tG,    g_tileG);
    cudaGetSymbolAddress((void**)&p_tM0,   g_tileM0);
    cudaGetSymbolAddress((void**)&p_tE,    g_tileE);
    cudaGetSymbolAddress((void**)&p_nG,    g_nGru);
    cudaGetSymbolAddress((void**)&p_tT,    g_tileT);
    cudaGetSymbolAddress((void**)&p_tM0a,  g_tileM0a);
    cudaGetSymbolAddress((void**)&p_tEa,   g_tileEa);
    cudaGetSymbolAddress((void**)&p_nA,    g_nAd);

    // weight re-layouts / conversions (f32 -> bf16)
    reorder_w1_k <<<216, 256>>>(c1w);
    reorder_w2_k <<<288, 256>>>(c2w);
    reorder_pre_k<<<512, 256>>>(prew);
    cvt4_k<<<(4*G3H*HH/4 + 255)/256, 256>>>(W_ih, p_Wih, 4*G3H*HH/4);
    cvt4_k<<<(8*HH*HH/4  + 255)/256, 256>>>(Wa,   p_Wa,  8*HH*HH/4);

    // embedding gathers (compact layout, 16B stores)
    embed_k<<<18816, 256>>>(obj, color, state, eo, ec, es);
    tail_k <<<768,   256>>>(dir, task, ed, et);

    // dynamic smem: 3 stages
    const int smem1 = 3 * (128 + 64)  * KS * 2;   // 46080
    const int smem2 = 3 * (128 + 128) * KS * 2;   // 61440
    cudaFuncSetAttribute(conv1_k, cudaFuncAttributeMaxDynamicSharedMemorySize, smem1);
    cudaFuncSetAttribute(conv2_k, cudaFuncAttributeMaxDynamicSharedMemorySize, smem2);
    cudaFuncSetAttribute(gemm_bf, cudaFuncAttributeMaxDynamicSharedMemorySize, smem2);

    // convs (implicit GEMM, bf16 mma + ldmatrix + 3-stage cp.async)
    conv1_k<<<3136, 256, smem1>>>(c1b);
    conv2_k<<<3136, 256, smem2>>>(c2b);

    // pre-linear: M=8192, N=512, K=6368, relu, bf16 out
    gemm_bf<<<dim3(64, 4), 256, smem2>>>(p_fused, FUSED, nullptr,
                                  p_preW, 0, preb, 0,
                                  nullptr, p_lat, HH, FUSED, 1, BB,
                                  nullptr, nullptr, nullptr, nullptr);

    // task sort
    sort_zero_k   <<<1,  32>>>();
    sort_count_k  <<<32, 256>>>(task);
    sort_off_k    <<<1,  1>>>();
    sort_scatter_k<<<32, 256>>>(task);

    // GRU gates: grouped (4 GRUs), perm gather; N=1536, K=512, f32 out
    gemm_bf<<<dim3(80, 12), 256, smem2>>>(p_lat, HH, p_perm,
                                   p_Wih, (long long)G3H*HH, b_ih, G3H,
                                   p_gx, nullptr, G3H, HH, 0, 0,
                                   p_tG, p_tM0, p_tE, p_nG);
    gru_elem_k<<<BB, HH>>>(b_hh);

    // adapter: grouped (8 tasks); N=512, K=512, relu, f32 out
    gemm_bf<<<dim3(80, 4), 256, smem2>>>(p_lat2, HH, nullptr,
                                  p_Wa, (long long)HH*HH, ba, HH,
                                  p_lat3, nullptr, HH, HH, 1, 0,
                                  p_tT, p_tM0a, p_tEa, p_nA);

    // policy heads + value
    heads_k<<<1024, 256>>>(Wh, bh2, vw, vb, out);
}

// round 12
// speedup vs baseline: 1.0049x; 1.0049x over previous
#include <cuda_runtime.h>
#include <cuda_bf16.h>
#include <math.h>
#include <stdint.h>

// ---------------------------------------------------------------------------
// Problem constants
// ---------------------------------------------------------------------------
#define BB     8192
#define NPOS   49
#define MCONV  (BB*NPOS)        // 401408
#define CI1    96
#define CO1    64
#define K1     (9*CI1)          // 864
#define CI2    64
#define CO2    128
#define K2     (9*CI2)          // 576
#define FUSED  6368
#define HH     512
#define G3H    1536
#define KS     40               // smem k-stride in bf16 (80B rows -> conflict-free)

typedef __nv_bfloat16 bf;

// ---------------------------------------------------------------------------
// Scratch (__device__ globals; zero-init at module load -> free SAME padding)
// ---------------------------------------------------------------------------
__device__ __align__(16) bf    g_xpad [BB*81*CI1];
__device__ __align__(16) bf    g_y1pad[BB*81*CI2];
__device__ __align__(16) bf    g_fused[BB*FUSED];
__device__ __align__(16) bf    g_W1re [CO1*K1];
__device__ __align__(16) bf    g_W2re [CO2*K2];
__device__ __align__(16) bf    g_preW [HH*FUSED];
__device__ __align__(16) bf    g_Wih  [4*G3H*HH];
__device__ __align__(16) bf    g_Wa   [8*HH*HH];
__device__ __align__(16) bf    g_lat  [BB*HH];
__device__ __align__(16) bf    g_gx   [BB*G3H];      // bf16 (was f32)
__device__ __align__(16) bf    g_lat2 [BB*HH];
__device__ __align__(16) bf    g_lat3 [BB*HH];       // bf16 (was f32)
__device__ int g_perm[BB], g_rowTask[BB];
__device__ int g_counts[8], g_cursor[8], g_off[9];
__device__ int g_tileG [80], g_tileM0 [80], g_tileE [80], g_nGru[1];
__device__ int g_tileT [80], g_tileM0a[80], g_tileEa[80], g_nAd[1];

// ---------------------------------------------------------------------------
// Helpers
// ---------------------------------------------------------------------------
__device__ __forceinline__ uint32_t pack_bf2(float lo, float hi) {
    __nv_bfloat162 p = __floats2bfloat162_rn(lo, hi);
    return *reinterpret_cast<uint32_t*>(&p);
}
__device__ __forceinline__ void cpa16(uint32_t dst, const void* src) {
    asm volatile("cp.async.cg.shared.global [%0], [%1], 16;\n"
                 :: "r"(dst), "l"(src));
}
__device__ __forceinline__ void cpa16p(uint32_t dst, const void* src, int sz) {
    asm volatile("cp.async.cg.shared.global [%0], [%1], 16, %2;\n"
                 :: "r"(dst), "l"(src), "r"(sz));
}
#define CP_COMMIT() asm volatile("cp.async.commit_group;\n" ::: "memory")
#define CP_WAIT0()  asm volatile("cp.async.wait_group 0;\n" ::: "memory")
#define CP_WAIT1()  asm volatile("cp.async.wait_group 1;\n" ::: "memory")

__device__ __forceinline__ void mma_bf16(float4& d,
    uint32_t a0, uint32_t a1, uint32_t a2, uint32_t a3,
    uint32_t b0, uint32_t b1)
{
    asm volatile(
        "mma.sync.aligned.m16n8k16.row.col.f32.bf16.bf16.f32 "
        "{%0,%1,%2,%3}, {%4,%5,%6,%7}, {%8,%9}, {%0,%1,%2,%3};\n"
        : "+f"(d.x), "+f"(d.y), "+f"(d.z), "+f"(d.w)
        : "r"(a0), "r"(a1), "r"(a2), "r"(a3), "r"(b0), "r"(b1));
}
__device__ __forceinline__ void ldm_x4(uint32_t (&r)[4], uint32_t addr) {
    asm volatile("ldmatrix.sync.aligned.m8n8.x4.shared.b16 {%0,%1,%2,%3}, [%4];"
                 : "=r"(r[0]), "=r"(r[1]), "=r"(r[2]), "=r"(r[3]) : "r"(addr));
}

// One k32 tile of MMAs over MF*16 x NF*8 warp tile, ldmatrix fragment loads.
template<int MF, int NF>
__device__ __forceinline__ void tile_mma_ldm(
    uint32_t sA, uint32_t sB, int mBase, int nBase, int lane,
    float4 (&acc)[MF][NF])
{
    int la = lane & 15, ka = lane >> 4;                 // A: row-in-16, k-half
    int nb = (lane & 7) + ((lane >> 4) << 3);           // B: n-row
    int kb = (lane >> 3) & 1;                           // B: k-half
#pragma unroll
    for (int ks = 0; ks < 2; ks++) {
        uint32_t b[NF][2];
#pragma unroll
        for (int p = 0; p < NF/2; p++) {
            uint32_t r[4];
            ldm_x4(r, sB + ((nBase + p*16 + nb)*KS + ks*16 + kb*8)*2);
            b[2*p  ][0] = r[0]; b[2*p  ][1] = r[1];
            b[2*p+1][0] = r[2]; b[2*p+1][1] = r[3];
        }
#pragma unroll
        for (int mf = 0; mf < MF; mf++) {
            uint32_t a[4];
            ldm_x4(a, sA + ((mBase + mf*16 + la)*KS + ks*16 + ka*8)*2);
#pragma unroll
            for (int nf = 0; nf < NF; nf++)
                mma_bf16(acc[mf][nf], a[0], a[1], a[2], a[3],
                         b[nf][0], b[nf][1]);
        }
    }
}

// ---------------------------------------------------------------------------
// Weight re-layout / conversion kernels
// ---------------------------------------------------------------------------
__global__ void reorder_w1_k(const float* __restrict__ w) {
    int idx = blockIdx.x * blockDim.x + threadIdx.x;
    int n = idx / K1, k = idx % K1;
    int t = k / CI1, i = k % CI1;
    g_W1re[idx] = __float2bfloat16(w[(n*CI1 + i)*9 + t]);
}
__global__ void reorder_w2_k(const float* __restrict__ w) {
    int idx = blockIdx.x * blockDim.x + threadIdx.x;
    int n = idx / K2, k = idx % K2;
    int t = k / CI2, i = k % CI2;
    g_W2re[idx] = __float2bfloat16(w[(n*CI2 + i)*9 + t]);
}
// one block per output row n: stage the row in smem, both sides coalesced
__global__ __launch_bounds__(256) void reorder_pre_k(const float* __restrict__ w) {
    __shared__ float buf[FUSED];
    int n = blockIdx.x;
    for (int k = threadIdx.x; k < FUSED; k += 256) buf[k] = w[n*FUSED + k];
    __syncthreads();
    for (int k = threadIdx.x; k < FUSED; k += 256) {
        int src;
        if (k < 6272) { int pos = k >> 7, ch = k & 127; src = ch*49 + pos; }
        else src = k;
        g_preW[n*FUSED + k] = __float2bfloat16(buf[src]);
    }
}
__global__ void cvt4_k(const float* __restrict__ src, bf* __restrict__ dst, int n4) {
    int i = blockIdx.x * blockDim.x + threadIdx.x;
    if (i >= n4) return;
    float4 v = *(const float4*)(src + i*4);
    uint2 o; o.x = pack_bf2(v.x, v.y); o.y = pack_bf2(v.z, v.w);
    *(uint2*)(dst + i*4) = o;
}

// ---------------------------------------------------------------------------
// Embedding gather -> padded activation [B][9*9][96] bf16
// ---------------------------------------------------------------------------
__global__ void embed_k(const int* __restrict__ obj, const int* __restrict__ col,
                        const int* __restrict__ sta,
                        const float* __restrict__ eo, const float* __restrict__ ec,
                        const float* __restrict__ es) {
    long idx = (long)blockIdx.x * blockDim.x + threadIdx.x;
    int sub = (int)(idx % 24);
    long cell = idx / 24;
    int b = (int)(cell / 49), pos = (int)(cell % 49);
    int r = pos / 7, c = pos % 7;
    int tbl = sub >> 3, j = sub & 7;
    int e; const float* tab;
    if (tbl == 0)      { e = obj[cell]; tab = eo; }
    else if (tbl == 1) { e = col[cell]; tab = ec; }
    else               { e = sta[cell]; tab = es; }
    float4 v = *(const float4*)(tab + e*32 + j*4);
    uint2 o; o.x = pack_bf2(v.x, v.y); o.y = pack_bf2(v.z, v.w);
    *(uint2*)(g_xpad + ((long)(b*81 + (r+1)*9 + (c+1)))*CI1 + tbl*32 + j*4) = o;
}

__global__ void tail_k(const int* __restrict__ dir, const int* __restrict__ task,
                       const float* __restrict__ ed, const float* __restrict__ et) {
    int idx = blockIdx.x * blockDim.x + threadIdx.x;
    int b = idx / 24, sub = idx % 24;
    float4 v; int dst;
    if (sub < 8) { v = *(const float4*)(ed + dir[b]*32 + sub*4);  dst = 6272 + sub*4; }
    else { int j = sub - 8; v = *(const float4*)(et + task[b]*64 + j*4); dst = 6304 + j*4; }
    uint2 o; o.x = pack_bf2(v.x, v.y); o.y = pack_bf2(v.z, v.w);
    *(uint2*)(g_fused + (long)b*FUSED + dst) = o;
}

// ---------------------------------------------------------------------------
// conv1: implicit GEMM  M=401408, N=64, K=864 -> relu -> y1pad interior
// CTA 128x64, 8 warps (4x2), warp tile 32x32; 3-stage cp.async, 1 sync/tile
// ---------------------------------------------------------------------------
__global__ __launch_bounds__(256) void conv1_k(const float* __restrict__ bias) {
    extern __shared__ __align__(16) bf smem1[];
    const int stageE = (128 + 64)*KS;          // bf16 elements per stage
    int m0 = blockIdx.x * 128;
    int tid = threadIdx.x;
    int warp = tid >> 5, lane = tid & 31;
    int lq = lane >> 2, lr = lane & 3;
    int mBase = (warp >> 1) * 32, nBase = (warp & 1) * 32;
    uint32_t sbase = (uint32_t)__cvta_generic_to_shared(smem1);

    float4 acc[2][4];
#pragma unroll
    for (int i = 0; i < 2; i++)
#pragma unroll
        for (int j = 0; j < 4; j++) acc[i][j] = make_float4(0.f,0.f,0.f,0.f);

    const int KT = K1/32;                       // 27
    auto load_tile = [&](int kt, int buf) {
        int k0 = kt*32;
        int tap = k0 / CI1;
        int i0  = k0 - tap*CI1;
        int offp = ((tap/3)*9 + (tap%3)) * CI1;
        uint32_t sb = sbase + buf*stageE*2;
#pragma unroll
        for (int it = 0; it < 3; it++) {
            int c = tid + it*256;               // 768 16B chunks
            const bf* src; uint32_t dst;
            if (c < 512) {
                int row = c >> 2, kc = c & 3;
                int m = m0 + row;
                int b = m/49, pos = m%49, r = pos/7, cc = pos%7;
                src = g_xpad + (long)(b*81 + r*9 + cc)*CI1 + offp + i0 + kc*8;
                dst = sb + (row*KS + kc*8)*2;
            } else {
                int row = (c - 512) >> 2, kc = c & 3;
                src = g_W1re + row*K1 + k0 + kc*8;
                dst = sb + (128*KS + row*KS + kc*8)*2;
            }
            cpa16(dst, src);
        }
        CP_COMMIT();
    };

    load_tile(0, 0); load_tile(1, 1);
    for (int kt = 0; kt < KT; kt++) {
        if (kt + 1 < KT) { CP_WAIT1(); } else { CP_WAIT0(); }
        __syncthreads();
        if (kt + 2 < KT) load_tile(kt + 2, (kt + 2) % 3);
        uint32_t sA = sbase + (kt % 3)*stageE*2;
        tile_mma_ldm<2,4>(sA, sA + 128*KS*2, mBase, nBase, lane, acc);
    }

#pragma unroll
    for (int mf = 0; mf < 2; mf++) {
#pragma unroll
        for (int half = 0; half < 2; half++) {
            int m = m0 + mBase + mf*16 + lq + half*8;
            int b = m/49, pos = m%49, r = pos/7, c = pos%7;
            bf* dst = g_y1pad + (long)(b*81 + (r+1)*9 + (c+1)) * CI2;
#pragma unroll
            for (int nf = 0; nf < 4; nf++) {
                int n = nBase + nf*8 + lr*2;
                float x0 = (half ? acc[mf][nf].z : acc[mf][nf].x) + bias[n];
                float x1 = (half ? acc[mf][nf].w : acc[mf][nf].y) + bias[n+1];
                *(uint32_t*)(dst + n) = pack_bf2(fmaxf(x0,0.f), fmaxf(x1,0.f));
            }
        }
    }
}

// ---------------------------------------------------------------------------
// conv2: implicit GEMM  M=401408, N=128, K=576 -> relu -> fused[pos*128+ch]
// CTA 128x128, 8 warps (2x4), warp tile 64x32; 3-stage, 1 sync/tile
// ---------------------------------------------------------------------------
__global__ __launch_bounds__(256) void conv2_k(const float* __restrict__ bias) {
    extern __shared__ __align__(16) bf smem2[];
    const int stageE = (128 + 128)*KS;
    int m0 = blockIdx.x * 128;
    int tid = threadIdx.x;
    int warp = tid >> 5, lane = tid & 31;
    int lq = lane >> 2, lr = lane & 3;
    int mBase = (warp >> 2) * 64, nBase = (warp & 3) * 32;
    uint32_t sbase = (uint32_t)__cvta_generic_to_shared(smem2);

    float4 acc[4][4];
#pragma unroll
    for (int i = 0; i < 4; i++)
#pragma unroll
        for (int j = 0; j < 4; j++) acc[i][j] = make_float4(0.f,0.f,0.f,0.f);

    const int KT = K2/32;                       // 18
    auto load_tile = [&](int kt, int buf) {
        int k0 = kt*32;
        int tap = k0 / CI2;
        int i0  = k0 - tap*CI2;
        int offp = ((tap/3)*9 + (tap%3)) * CI2;
        uint32_t sb = sbase + buf*stageE*2;
#pragma unroll
        for (int it = 0; it < 4; it++) {
            int c = tid + it*256;               // 1024 16B chunks
            const bf* src; uint32_t dst;
            if (c < 512) {
                int row = c >> 2, kc = c & 3;
                int m = m0 + row;
                int b = m/49, pos = m%49, r = pos/7, cc = pos%7;
                src = g_y1pad + (long)(b*81 + r*9 + cc)*CI2 + offp + i0 + kc*8;
                dst = sb + (row*KS + kc*8)*2;
            } else {
                int row = (c - 512) >> 2, kc = c & 3;
                src = g_W2re + row*K2 + k0 + kc*8;
                dst = sb + (128*KS + row*KS + kc*8)*2;
            }
            cpa16(dst, src);
        }
        CP_COMMIT();
    };

    load_tile(0, 0); load_tile(1, 1);
    for (int kt = 0; kt < KT; kt++) {
        if (kt + 1 < KT) { CP_WAIT1(); } else { CP_WAIT0(); }
        __syncthreads();
        if (kt + 2 < KT) load_tile(kt + 2, (kt + 2) % 3);
        uint32_t sA = sbase + (kt % 3)*stageE*2;
        tile_mma_ldm<4,4>(sA, sA + 128*KS*2, mBase, nBase, lane, acc);
    }

#pragma unroll
    for (int mf = 0; mf < 4; mf++) {
#pragma unroll
        for (int half = 0; half < 2; half++) {
            int m = m0 + mBase + mf*16 + lq + half*8;
            int b = m/49, pos = m%49;
            bf* dst = g_fused + (long)b*FUSED + pos*128;
#pragma unroll
            for (int nf = 0; nf < 4; nf++) {
                int n = nBase + nf*8 + lr*2;
                float x0 = (half ? acc[mf][nf].z : acc[mf][nf].x) + bias[n];
                float x1 = (half ? acc[mf][nf].w : acc[mf][nf].y) + bias[n+1];
                *(uint32_t*)(dst + n) = pack_bf2(fmaxf(x0,0.f), fmaxf(x1,0.f));
            }
        }
    }
}

// ---------------------------------------------------------------------------
// Generic TN GEMM (bf16 MMA, 3-stage cp.async, ldmatrix):
// C[m,n] = act( sum_k A[m,k]*W[n,k] + bias[n] ); optional perm gather,
// grouped M-tiles; bf16 output.  CTA 128x128.
// ---------------------------------------------------------------------------
__global__ __launch_bounds__(256) void gemm_bf(
    const bf* __restrict__ A, int lda,
    const int* __restrict__ perm,
    const bf* __restrict__ Wg, long long wStride,
    const float* __restrict__ biasg, int biasStride,
    bf* __restrict__ Cb, int ldc,
    int K, int relu, int denseM,
    const int* __restrict__ tileG, const int* __restrict__ tileM0,
    const int* __restrict__ tileE, const int* __restrict__ nTilesPtr)
{
    extern __shared__ __align__(16) bf smemg[];
    const int stageE = (128 + 128)*KS;
    int m0, mEnd, g;
    if (tileG) {
        int t = blockIdx.x;
        if (t >= *nTilesPtr) return;
        g = tileG[t]; m0 = tileM0[t]; mEnd = tileE[t];
    } else {
        g = 0; m0 = blockIdx.x * 128; mEnd = denseM;
    }
    const bf* W = Wg + (long long)g * wStride;
    const float* bias = biasg + g * biasStride;
    int n0 = blockIdx.y * 128;

    int tid = threadIdx.x;
    int warp = tid >> 5, lane = tid & 31;
    int lq = lane >> 2, lr = lane & 3;
    int mBase = (warp >> 2) * 64, nBase = (warp & 3) * 32;
    uint32_t sbase = (uint32_t)__cvta_generic_to_shared(smemg);

    float4 acc[4][4];
#pragma unroll
    for (int i = 0; i < 4; i++)
#pragma unroll
        for (int j = 0; j < 4; j++) acc[i][j] = make_float4(0.f,0.f,0.f,0.f);

    const int KT = K/32;
    auto load_tile = [&](int kt, int buf) {
        int k0 = kt*32;
        uint32_t sb = sbase + buf*stageE*2;
#pragma unroll
        for (int it = 0; it < 4; it++) {
            int c = tid + it*256;
            const bf* src; uint32_t dst; int sz = 16;
            if (c < 512) {
                int row = c >> 2, kc = c & 3;
                int m = m0 + row;
                long ar = 0;
                if (m < mEnd) ar = perm ? perm[m] : m; else sz = 0;
                src = A + ar*lda + k0 + kc*8;
                dst = sb + (row*KS + kc*8)*2;
            } else {
                int row = (c - 512) >> 2, kc = c & 3;
                src = W + (long)(n0 + row)*K + k0 + kc*8;
                dst = sb + (128*KS + row*KS + kc*8)*2;
            }
            cpa16p(dst, src, sz);
        }
        CP_COMMIT();
    };

    load_tile(0, 0); load_tile(1, 1);
    for (int kt = 0; kt < KT; kt++) {
        if (kt + 1 < KT) { CP_WAIT1(); } else { CP_WAIT0(); }
        __syncthreads();
        if (kt + 2 < KT) load_tile(kt + 2, (kt + 2) % 3);
        uint32_t sA = sbase + (kt % 3)*stageE*2;
        tile_mma_ldm<4,4>(sA, sA + 128*KS*2, mBase, nBase, lane, acc);
    }

#pragma unroll
    for (int mf = 0; mf < 4; mf++) {
#pragma unroll
        for (int half = 0; half < 2; half++) {
            int m = m0 + mBase + mf*16 + lq + half*8;
            if (m >= mEnd) continue;
#pragma unroll
            for (int nf = 0; nf < 4; nf++) {
                int n = n0 + nBase + nf*8 + lr*2;
                float x0 = (half ? acc[mf][nf].z : acc[mf][nf].x) + bias[n];
                float x1 = (half ? acc[mf][nf].w : acc[mf][nf].y) + bias[n+1];
                if (relu) { x0 = fmaxf(x0, 0.f); x1 = fmaxf(x1, 0.f); }
                *(uint32_t*)(Cb + (long)m*ldc + n) = pack_bf2(x0, x1);
            }
        }
    }
}

// ---------------------------------------------------------------------------
// Task sort / compaction
// ---------------------------------------------------------------------------
__global__ void sort_zero_k() {
    int t = threadIdx.x;
    if (t < 8) { g_counts[t] = 0; g_cursor[t] = 0; }
}
__global__ void sort_count_k(const int* __restrict__ task) {
    int b = blockIdx.x * blockDim.x + threadIdx.x;
    if (b < BB) atomicAdd(&g_counts[task[b]], 1);
}
__global__ void sort_off_k() {
    if (threadIdx.x == 0 && blockIdx.x == 0) {
        int off = 0;
        for (int t = 0; t < 8; t++) { g_off[t] = off; off += g_counts[t]; }
        g_off[8] = off;
        int idx = 0;
        for (int g = 0; g < 4; g++) {
            int s = g_off[g];
            int e = (g < 3) ? g_off[g+1] : BB;
            for (int m0 = s; m0 < e; m0 += 128) {
                g_tileG[idx] = g; g_tileM0[idx] = m0; g_tileE[idx] = e; idx++;
            }
        }
        g_nGru[0] = idx;
        idx = 0;
        for (int t = 0; t < 8; t++) {
            int s = g_off[t], e = g_off[t+1];
            for (int m0 = s; m0 < e; m0 += 128) {
                g_tileT[idx] = t; g_tileM0a[idx] = m0; g_tileEa[idx] = e; idx++;
            }
        }
        g_nAd[0] = idx;
    }
}
__global__ void sort_scatter_k(const int* __restrict__ task) {
    int b = blockIdx.x * blockDim.x + threadIdx.x;
    if (b < BB) {
        int t = task[b];
        int p = g_off[t] + atomicAdd(&g_cursor[t], 1);
        g_perm[p] = b;
        g_rowTask[p] = t;
    }
}

// ---------------------------------------------------------------------------
// GRU elementwise (h0 = 0):  lat2 = (1 - z) * tanh(nx + r*nh)   (bf16 gx in)
// ---------------------------------------------------------------------------
__global__ void gru_elem_k(const float* __restrict__ b_hh) {
    int p = blockIdx.x, h = threadIdx.x;
    int t = g_rowTask[p];
    int g = (t < 3) ? t : 3;
    const bf* gxr = g_gx + (long)p*G3H;
    const float* bh = b_hh + g*G3H;
    float rx = __bfloat162float(gxr[h]);
    float zx = __bfloat162float(gxr[512 + h]);
    float nx = __bfloat162float(gxr[1024 + h]);
    float r = 1.f / (1.f + expf(-(rx + bh[h])));
    float z = 1.f / (1.f + expf(-(zx + bh[512 + h])));
    float n = tanhf(nx + r * bh[1024 + h]);
    g_lat2[(long)p*HH + h] = __float2bfloat16((1.f - z) * n);
}

// ---------------------------------------------------------------------------
// Heads: 7 logits + value per sample, scattered to original order (bf16 lat3)
// ---------------------------------------------------------------------------
__global__ void heads_k(const float* __restrict__ Wh, const float* __restrict__ bh2,
                        const float* __restrict__ vw, const float* __restrict__ vb,
                        float* __restrict__ out) {
    int p = blockIdx.x * 8 + (threadIdx.x >> 5);
    int lane = threadIdx.x & 31;
    if (p >= BB) return;
    int t = g_rowTask[p];
    int borig = g_perm[p];
    const bf* lrow = g_lat3 + (long)p*HH;
    const float* wt = Wh + t*7*HH;
    float acc[8];
#pragma unroll
    for (int a = 0; a < 8; a++) acc[a] = 0.f;
    for (int h = lane; h < HH; h += 32) {
        float x = __bfloat162float(lrow[h]);
#pragma unroll
        for (int a = 0; a < 7; a++) acc[a] += x * wt[a*HH + h];
        acc[7] += x * vw[h];
    }
#pragma unroll
    for (int a = 0; a < 8; a++)
#pragma unroll
        for (int off = 16; off; off >>= 1)
            acc[a] += __shfl_down_sync(0xffffffff, acc[a], off);
    if (lane == 0) {
#pragma unroll
        for (int a = 0; a < 7; a++) out[borig*7 + a] = acc[a] + bh2[t*7 + a];
        out[BB*7 + borig] = acc[7] + vb[0];
    }
}

// ---------------------------------------------------------------------------
// Launch
// ---------------------------------------------------------------------------
extern "C" void kernel_launch(void* const* d_in, const int* in_sizes, int n_in,
                              void* d_out, int out_size) {
    const int*   obj   = (const int*)  d_in[0];
    const int*   color = (const int*)  d_in[1];
    const int*   state = (const int*)  d_in[2];
    const int*   dir   = (const int*)  d_in[3];
    const int*   task  = (const int*)  d_in[4];
    const float* eo    = (const float*)d_in[5];
    const float* ec    = (const float*)d_in[6];
    const float* es    = (const float*)d_in[7];
    const float* ed    = (const float*)d_in[8];
    const float* et    = (const float*)d_in[9];
    const float* c1w   = (const float*)d_in[10];
    const float* c1b   = (const float*)d_in[11];
    const float* c2w   = (const float*)d_in[12];
    const float* c2b   = (const float*)d_in[13];
    const float* prew  = (const float*)d_in[14];
    const float* preb  = (const float*)d_in[15];
    const float* W_ih  = (const float*)d_in[16];
    const float* b_ih  = (const float*)d_in[18];
    const float* b_hh  = (const float*)d_in[19];
    const float* Wa    = (const float*)d_in[20];
    const float* ba    = (const float*)d_in[21];
    const float* Wh    = (const float*)d_in[22];
    const float* bh2   = (const float*)d_in[23];
    const float* vw    = (const float*)d_in[24];
    const float* vb    = (const float*)d_in[25];
    float* out = (float*)d_out;

    bf *p_fused, *p_preW, *p_lat, *p_lat2, *p_lat3, *p_gx, *p_Wih, *p_Wa;
    int *p_perm, *p_tG, *p_tM0, *p_tE, *p_nG, *p_tT, *p_tM0a, *p_tEa, *p_nA;
    cudaGetSymbolAddress((void**)&p_fused, g_fused);
    cudaGetSymbolAddress((void**)&p_preW,  g_preW);
    cudaGetSymbolAddress((void**)&p_lat,   g_lat);
    cudaGetSymbolAddress((void**)&p_gx,    g_gx);
    cudaGetSymbolAddress((void**)&p_lat2,  g_lat2);
    cudaGetSymbolAddress((void**)&p_lat3,  g_lat3);
    cudaGetSymbolAddress((void**)&p_Wih,   g_Wih);
    cudaGetSymbolAddress((void**)&p_Wa,    g_Wa);
    cudaGetSymbolAddress((void**)&p_perm,  g_perm);
    cudaGetSymbolAddress((void**)&p_tG,    g_tileG);
    cudaGetSymbolAddress((void**)&p_tM0,   g_tileM0);
    cudaGetSymbolAddress((void**)&p_tE,    g_tileE);
    cudaGetSymbolAddress((void**)&p_nG,    g_nGru);
    cudaGetSymbolAddress((void**)&p_tT,    g_tileT);
    cudaGetSymbolAddress((void**)&p_tM0a,  g_tileM0a);
    cudaGetSymbolAddress((void**)&p_tEa,   g_tileEa);
    cudaGetSymbolAddress((void**)&p_nA,    g_nAd);

    // weight re-layouts / conversions (f32 -> bf16)
    reorder_w1_k <<<216, 256>>>(c1w);
    reorder_w2_k <<<288, 256>>>(c2w);
    reorder_pre_k<<<512, 256>>>(prew);
    cvt4_k<<<(4*G3H*HH/4 + 255)/256, 256>>>(W_ih, p_Wih, 4*G3H*HH/4);
    cvt4_k<<<(8*HH*HH/4  + 255)/256, 256>>>(Wa,   p_Wa,  8*HH*HH/4);

    // embedding gathers
    embed_k<<<37632, 256>>>(obj, color, state, eo, ec, es);
    tail_k <<<768,   256>>>(dir, task, ed, et);

    // dynamic smem: 3 stages
    const int smem1 = 3 * (128 + 64)  * KS * 2;   // 46080
    const int smem2 = 3 * (128 + 128) * KS * 2;   // 61440
    cudaFuncSetAttribute(conv1_k, cudaFuncAttributeMaxDynamicSharedMemorySize, smem1);
    cudaFuncSetAttribute(conv2_k, cudaFuncAttributeMaxDynamicSharedMemorySize, smem2);
    cudaFuncSetAttribute(gemm_bf, cudaFuncAttributeMaxDynamicSharedMemorySize, smem2);

    // convs (implicit GEMM, bf16 mma + ldmatrix + 3-stage cp.async)
    conv1_k<<<3136, 256, smem1>>>(c1b);
    conv2_k<<<3136, 256, smem2>>>(c2b);

    // pre-linear: M=8192, N=512, K=6368, relu, bf16 out
    gemm_bf<<<dim3(64, 4), 256, smem2>>>(p_fused, FUSED, nullptr,
                                  p_preW, 0, preb, 0,
                                  p_lat, HH, FUSED, 1, BB,
                                  nullptr, nullptr, nullptr, nullptr);

    // task sort
    sort_zero_k   <<<1,  32>>>();
    sort_count_k  <<<32, 256>>>(task);
    sort_off_k    <<<1,  1>>>();
    sort_scatter_k<<<32, 256>>>(task);

    // GRU gates: grouped (4 GRUs), perm gather; N=1536, K=512, bf16 out
    gemm_bf<<<dim3(80, 12), 256, smem2>>>(p_lat, HH, p_perm,
                                   p_Wih, (long long)G3H*HH, b_ih, G3H,
                                   p_gx, G3H, HH, 0, 0,
                                   p_tG, p_tM0, p_tE, p_nG);
    gru_elem_k<<<BB, HH>>>(b_hh);

    // adapter: grouped (8 tasks); N=512, K=512, relu, bf16 out
    gemm_bf<<<dim3(80, 4), 256, smem2>>>(p_lat2, HH, nullptr,
                                  p_Wa, (long long)HH*HH, ba, HH,
                                  p_lat3, HH, HH, 1, 0,
                                  p_tT, p_tM0a, p_tEa, p_nA);

    // policy heads + value
    heads_k<<<1024, 256>>>(Wh, bh2, vw, vb, out);
}

// round 13
// speedup vs baseline: 1.0232x; 1.0182x over previous
#include <cuda_runtime.h>
#include <cuda_bf16.h>
#include <math.h>
#include <stdint.h>

// ---------------------------------------------------------------------------
// Problem constants
// ---------------------------------------------------------------------------
#define BB     8192
#define NPOS   49
#define MCONV  (BB*NPOS)        // 401408
#define CI1    96
#define CO1    64
#define K1     (9*CI1)          // 864
#define CI2    64
#define CO2    128
#define K2     (9*CI2)          // 576
#define FUSED  6368
#define HH     512
#define G3H    1536
#define KS     40               // smem k-stride in bf16 (80B rows -> conflict-free)

typedef __nv_bfloat16 bf;

// ---------------------------------------------------------------------------
// Scratch (__device__ globals; zero-init at module load -> free SAME padding)
// ---------------------------------------------------------------------------
__device__ __align__(16) bf    g_xpad [BB*81*CI1];
__device__ __align__(16) bf    g_y1pad[BB*81*CI2];
__device__ __align__(16) bf    g_fused[BB*FUSED];
__device__ __align__(16) bf    g_W1re [CO1*K1];
__device__ __align__(16) bf    g_W2re [CO2*K2];
__device__ __align__(16) bf    g_preW [HH*FUSED];
__device__ __align__(16) bf    g_Wih  [4*G3H*HH];
__device__ __align__(16) bf    g_Wa   [8*HH*HH];
__device__ __align__(16) bf    g_lat  [BB*HH];
__device__ __align__(16) float g_gx   [BB*G3H];
__device__ __align__(16) bf    g_lat2 [BB*HH];
__device__ __align__(16) float g_lat3 [BB*HH];
__device__ int g_perm[BB], g_rowTask[BB];
__device__ int g_counts[8], g_off[9];
__device__ int g_tileG [80], g_tileM0 [80], g_tileE [80], g_nGru[1];
__device__ int g_tileT [80], g_tileM0a[80], g_tileEa[80], g_nAd[1];

// ---------------------------------------------------------------------------
// Helpers
// ---------------------------------------------------------------------------
__device__ __forceinline__ uint32_t pack_bf2(float lo, float hi) {
    __nv_bfloat162 p = __floats2bfloat162_rn(lo, hi);
    return *reinterpret_cast<uint32_t*>(&p);
}
__device__ __forceinline__ void cpa16(uint32_t dst, const void* src) {
    asm volatile("cp.async.cg.shared.global [%0], [%1], 16;\n"
                 :: "r"(dst), "l"(src));
}
__device__ __forceinline__ void cpa16p(uint32_t dst, const void* src, int sz) {
    asm volatile("cp.async.cg.shared.global [%0], [%1], 16, %2;\n"
                 :: "r"(dst), "l"(src), "r"(sz));
}
#define CP_COMMIT() asm volatile("cp.async.commit_group;\n" ::: "memory")
#define CP_WAIT0()  asm volatile("cp.async.wait_group 0;\n" ::: "memory")
#define CP_WAIT1()  asm volatile("cp.async.wait_group 1;\n" ::: "memory")

__device__ __forceinline__ void mma_bf16(float4& d,
    uint32_t a0, uint32_t a1, uint32_t a2, uint32_t a3,
    uint32_t b0, uint32_t b1)
{
    asm volatile(
        "mma.sync.aligned.m16n8k16.row.col.f32.bf16.bf16.f32 "
        "{%0,%1,%2,%3}, {%4,%5,%6,%7}, {%8,%9}, {%0,%1,%2,%3};\n"
        : "+f"(d.x), "+f"(d.y), "+f"(d.z), "+f"(d.w)
        : "r"(a0), "r"(a1), "r"(a2), "r"(a3), "r"(b0), "r"(b1));
}
__device__ __forceinline__ void ldm_x4(uint32_t (&r)[4], uint32_t addr) {
    asm volatile("ldmatrix.sync.aligned.m8n8.x4.shared.b16 {%0,%1,%2,%3}, [%4];"
                 : "=r"(r[0]), "=r"(r[1]), "=r"(r[2]), "=r"(r[3]) : "r"(addr));
}

// One k32 tile of MMAs over MF*16 x NF*8 warp tile, ldmatrix fragment loads.
template<int MF, int NF>
__device__ __forceinline__ void tile_mma_ldm(
    uint32_t sA, uint32_t sB, int mBase, int nBase, int lane,
    float4 (&acc)[MF][NF])
{
    int la = lane & 15, ka = lane >> 4;                 // A: row-in-16, k-half
    int nb = (lane & 7) + ((lane >> 4) << 3);           // B: n-row
    int kb = (lane >> 3) & 1;                           // B: k-half
#pragma unroll
    for (int ks = 0; ks < 2; ks++) {
        uint32_t b[NF][2];
#pragma unroll
        for (int p = 0; p < NF/2; p++) {
            uint32_t r[4];
            ldm_x4(r, sB + ((nBase + p*16 + nb)*KS + ks*16 + kb*8)*2);
            b[2*p  ][0] = r[0]; b[2*p  ][1] = r[1];
            b[2*p+1][0] = r[2]; b[2*p+1][1] = r[3];
        }
#pragma unroll
        for (int mf = 0; mf < MF; mf++) {
            uint32_t a[4];
            ldm_x4(a, sA + ((mBase + mf*16 + la)*KS + ks*16 + ka*8)*2);
#pragma unroll
            for (int nf = 0; nf < NF; nf++)
                mma_bf16(acc[mf][nf], a[0], a[1], a[2], a[3],
                         b[nf][0], b[nf][1]);
        }
    }
}

// ---------------------------------------------------------------------------
// Weight re-layout / conversion kernels
// ---------------------------------------------------------------------------
__global__ void reorder_w1_k(const float* __restrict__ w) {
    int idx = blockIdx.x * blockDim.x + threadIdx.x;
    int n = idx / K1, k = idx % K1;
    int t = k / CI1, i = k % CI1;
    g_W1re[idx] = __float2bfloat16(w[(n*CI1 + i)*9 + t]);
}
__global__ void reorder_w2_k(const float* __restrict__ w) {
    int idx = blockIdx.x * blockDim.x + threadIdx.x;
    int n = idx / K2, k = idx % K2;
    int t = k / CI2, i = k % CI2;
    g_W2re[idx] = __float2bfloat16(w[(n*CI2 + i)*9 + t]);
}
// one block per output row n: stage the row in smem, both sides coalesced
__global__ __launch_bounds__(256) void reorder_pre_k(const float* __restrict__ w) {
    __shared__ float buf[FUSED];
    int n = blockIdx.x;
    for (int k = threadIdx.x; k < FUSED; k += 256) buf[k] = w[n*FUSED + k];
    __syncthreads();
    for (int k = threadIdx.x; k < FUSED; k += 256) {
        int src;
        if (k < 6272) { int pos = k >> 7, ch = k & 127; src = ch*49 + pos; }
        else src = k;
        g_preW[n*FUSED + k] = __float2bfloat16(buf[src]);
    }
}
// one launch converting both W_ih (4*G3H*HH) and Wa (8*HH*HH) to bf16
#define N4_WIH (4*G3H*HH/4)
#define N4_WA  (8*HH*HH/4)
__global__ void cvt_w_k(const float* __restrict__ wih, const float* __restrict__ wa) {
    int i = blockIdx.x * blockDim.x + threadIdx.x;
    const float* src; bf* dst;
    if (i < N4_WIH) { src = wih + i*4; dst = g_Wih + i*4; }
    else {
        int j = i - N4_WIH;
        if (j >= N4_WA) return;
        src = wa + j*4; dst = g_Wa + j*4;
    }
    float4 v = *(const float4*)src;
    uint2 o; o.x = pack_bf2(v.x, v.y); o.y = pack_bf2(v.z, v.w);
    *(uint2*)dst = o;
}

// ---------------------------------------------------------------------------
// Embedding gather -> padded activation [B][9*9][96] bf16
// ---------------------------------------------------------------------------
__global__ void embed_k(const int* __restrict__ obj, const int* __restrict__ col,
                        const int* __restrict__ sta,
                        const float* __restrict__ eo, const float* __restrict__ ec,
                        const float* __restrict__ es) {
    long idx = (long)blockIdx.x * blockDim.x + threadIdx.x;
    int sub = (int)(idx % 24);
    long cell = idx / 24;
    int b = (int)(cell / 49), pos = (int)(cell % 49);
    int r = pos / 7, c = pos % 7;
    int tbl = sub >> 3, j = sub & 7;
    int e; const float* tab;
    if (tbl == 0)      { e = obj[cell]; tab = eo; }
    else if (tbl == 1) { e = col[cell]; tab = ec; }
    else               { e = sta[cell]; tab = es; }
    float4 v = *(const float4*)(tab + e*32 + j*4);
    uint2 o; o.x = pack_bf2(v.x, v.y); o.y = pack_bf2(v.z, v.w);
    *(uint2*)(g_xpad + ((long)(b*81 + (r+1)*9 + (c+1)))*CI1 + tbl*32 + j*4) = o;
}

__global__ void tail_k(const int* __restrict__ dir, const int* __restrict__ task,
                       const float* __restrict__ ed, const float* __restrict__ et) {
    int idx = blockIdx.x * blockDim.x + threadIdx.x;
    int b = idx / 24, sub = idx % 24;
    float4 v; int dst;
    if (sub < 8) { v = *(const float4*)(ed + dir[b]*32 + sub*4);  dst = 6272 + sub*4; }
    else { int j = sub - 8; v = *(const float4*)(et + task[b]*64 + j*4); dst = 6304 + j*4; }
    uint2 o; o.x = pack_bf2(v.x, v.y); o.y = pack_bf2(v.z, v.w);
    *(uint2*)(g_fused + (long)b*FUSED + dst) = o;
}

// ---------------------------------------------------------------------------
// conv1: implicit GEMM  M=401408, N=64, K=864 -> relu -> y1pad interior
// CTA 128x64, 8 warps (4x2), warp tile 32x32; 3-stage cp.async, 1 sync/tile
// ---------------------------------------------------------------------------
__global__ __launch_bounds__(256) void conv1_k(const float* __restrict__ bias) {
    extern __shared__ __align__(16) bf smem1[];
    const int stageE = (128 + 64)*KS;          // bf16 elements per stage
    int m0 = blockIdx.x * 128;
    int tid = threadIdx.x;
    int warp = tid >> 5, lane = tid & 31;
    int lq = lane >> 2, lr = lane & 3;
    int mBase = (warp >> 1) * 32, nBase = (warp & 1) * 32;
    uint32_t sbase = (uint32_t)__cvta_generic_to_shared(smem1);

    float4 acc[2][4];
#pragma unroll
    for (int i = 0; i < 2; i++)
#pragma unroll
        for (int j = 0; j < 4; j++) acc[i][j] = make_float4(0.f,0.f,0.f,0.f);

    const int KT = K1/32;                       // 27
    auto load_tile = [&](int kt, int buf) {
        int k0 = kt*32;
        int tap = k0 / CI1;
        int i0  = k0 - tap*CI1;
        int offp = ((tap/3)*9 + (tap%3)) * CI1;
        uint32_t sb = sbase + buf*stageE*2;
#pragma unroll
        for (int it = 0; it < 3; it++) {
            int c = tid + it*256;               // 768 16B chunks
            const bf* src; uint32_t dst;
            if (c < 512) {
                int row = c >> 2, kc = c & 3;
                int m = m0 + row;
                int b = m/49, pos = m%49, r = pos/7, cc = pos%7;
                src = g_xpad + (long)(b*81 + r*9 + cc)*CI1 + offp + i0 + kc*8;
                dst = sb + (row*KS + kc*8)*2;
            } else {
                int row = (c - 512) >> 2, kc = c & 3;
                src = g_W1re + row*K1 + k0 + kc*8;
                dst = sb + (128*KS + row*KS + kc*8)*2;
            }
            cpa16(dst, src);
        }
        CP_COMMIT();
    };

    load_tile(0, 0); load_tile(1, 1);
    for (int kt = 0; kt < KT; kt++) {
        if (kt + 1 < KT) { CP_WAIT1(); } else { CP_WAIT0(); }
        __syncthreads();
        if (kt + 2 < KT) load_tile(kt + 2, (kt + 2) % 3);
        uint32_t sA = sbase + (kt % 3)*stageE*2;
        tile_mma_ldm<2,4>(sA, sA + 128*KS*2, mBase, nBase, lane, acc);
    }

#pragma unroll
    for (int mf = 0; mf < 2; mf++) {
#pragma unroll
        for (int half = 0; half < 2; half++) {
            int m = m0 + mBase + mf*16 + lq + half*8;
            int b = m/49, pos = m%49, r = pos/7, c = pos%7;
            bf* dst = g_y1pad + (long)(b*81 + (r+1)*9 + (c+1)) * CI2;
#pragma unroll
            for (int nf = 0; nf < 4; nf++) {
                int n = nBase + nf*8 + lr*2;
                float x0 = (half ? acc[mf][nf].z : acc[mf][nf].x) + bias[n];
                float x1 = (half ? acc[mf][nf].w : acc[mf][nf].y) + bias[n+1];
                *(uint32_t*)(dst + n) = pack_bf2(fmaxf(x0,0.f), fmaxf(x1,0.f));
            }
        }
    }
}

// ---------------------------------------------------------------------------
// conv2: implicit GEMM  M=401408, N=128, K=576 -> relu -> fused[pos*128+ch]
// CTA 128x128, 8 warps (2x4), warp tile 64x32; 3-stage, 1 sync/tile
// ---------------------------------------------------------------------------
__global__ __launch_bounds__(256) void conv2_k(const float* __restrict__ bias) {
    extern __shared__ __align__(16) bf smem2[];
    const int stageE = (128 + 128)*KS;
    int m0 = blockIdx.x * 128;
    int tid = threadIdx.x;
    int warp = tid >> 5, lane = tid & 31;
    int lq = lane >> 2, lr = lane & 3;
    int mBase = (warp >> 2) * 64, nBase = (warp & 3) * 32;
    uint32_t sbase = (uint32_t)__cvta_generic_to_shared(smem2);

    float4 acc[4][4];
#pragma unroll
    for (int i = 0; i < 4; i++)
#pragma unroll
        for (int j = 0; j < 4; j++) acc[i][j] = make_float4(0.f,0.f,0.f,0.f);

    const int KT = K2/32;                       // 18
    auto load_tile = [&](int kt, int buf) {
        int k0 = kt*32;
        int tap = k0 / CI2;
        int i0  = k0 - tap*CI2;
        int offp = ((tap/3)*9 + (tap%3)) * CI2;
        uint32_t sb = sbase + buf*stageE*2;
#pragma unroll
        for (int it = 0; it < 4; it++) {
            int c = tid + it*256;               // 1024 16B chunks
            const bf* src; uint32_t dst;
            if (c < 512) {
                int row = c >> 2, kc = c & 3;
                int m = m0 + row;
                int b = m/49, pos = m%49, r = pos/7, cc = pos%7;
                src = g_y1pad + (long)(b*81 + r*9 + cc)*CI2 + offp + i0 + kc*8;
                dst = sb + (row*KS + kc*8)*2;
            } else {
                int row = (c - 512) >> 2, kc = c & 3;
                src = g_W2re + row*K2 + k0 + kc*8;
                dst = sb + (128*KS + row*KS + kc*8)*2;
            }
            cpa16(dst, src);
        }
        CP_COMMIT();
    };

    load_tile(0, 0); load_tile(1, 1);
    for (int kt = 0; kt < KT; kt++) {
        if (kt + 1 < KT) { CP_WAIT1(); } else { CP_WAIT0(); }
        __syncthreads();
        if (kt + 2 < KT) load_tile(kt + 2, (kt + 2) % 3);
        uint32_t sA = sbase + (kt % 3)*stageE*2;
        tile_mma_ldm<4,4>(sA, sA + 128*KS*2, mBase, nBase, lane, acc);
    }

#pragma unroll
    for (int mf = 0; mf < 4; mf++) {
#pragma unroll
        for (int half = 0; half < 2; half++) {
            int m = m0 + mBase + mf*16 + lq + half*8;
            int b = m/49, pos = m%49;
            bf* dst = g_fused + (long)b*FUSED + pos*128;
#pragma unroll
            for (int nf = 0; nf < 4; nf++) {
                int n = nBase + nf*8 + lr*2;
                float x0 = (half ? acc[mf][nf].z : acc[mf][nf].x) + bias[n];
                float x1 = (half ? acc[mf][nf].w : acc[mf][nf].y) + bias[n+1];
                *(uint32_t*)(dst + n) = pack_bf2(fmaxf(x0,0.f), fmaxf(x1,0.f));
            }
        }
    }
}

// ---------------------------------------------------------------------------
// Generic TN GEMM (bf16 MMA, 3-stage cp.async, ldmatrix):
// C[m,n] = act( sum_k A[m,k]*W[n,k] + bias[n] ); optional perm gather,
// grouped M-tiles; output f32 (Cf) or bf16 (Cb).  CTA 128x128.
// ---------------------------------------------------------------------------
__global__ __launch_bounds__(256) void gemm_bf(
    const bf* __restrict__ A, int lda,
    const int* __restrict__ perm,
    const bf* __restrict__ Wg, long long wStride,
    const float* __restrict__ biasg, int biasStride,
    float* __restrict__ Cf, bf* __restrict__ Cb, int ldc,
    int K, int relu, int denseM,
    const int* __restrict__ tileG, const int* __restrict__ tileM0,
    const int* __restrict__ tileE, const int* __restrict__ nTilesPtr)
{
    extern __shared__ __align__(16) bf smemg[];
    const int stageE = (128 + 128)*KS;
    int m0, mEnd, g;
    if (tileG) {
        int t = blockIdx.x;
        if (t >= *nTilesPtr) return;
        g = tileG[t]; m0 = tileM0[t]; mEnd = tileE[t];
    } else {
        g = 0; m0 = blockIdx.x * 128; mEnd = denseM;
    }
    const bf* W = Wg + (long long)g * wStride;
    const float* bias = biasg + g * biasStride;
    int n0 = blockIdx.y * 128;

    int tid = threadIdx.x;
    int warp = tid >> 5, lane = tid & 31;
    int lq = lane >> 2, lr = lane & 3;
    int mBase = (warp >> 2) * 64, nBase = (warp & 3) * 32;
    uint32_t sbase = (uint32_t)__cvta_generic_to_shared(smemg);

    float4 acc[4][4];
#pragma unroll
    for (int i = 0; i < 4; i++)
#pragma unroll
        for (int j = 0; j < 4; j++) acc[i][j] = make_float4(0.f,0.f,0.f,0.f);

    const int KT = K/32;
    auto load_tile = [&](int kt, int buf) {
        int k0 = kt*32;
        uint32_t sb = sbase + buf*stageE*2;
#pragma unroll
        for (int it = 0; it < 4; it++) {
            int c = tid + it*256;
            const bf* src; uint32_t dst; int sz = 16;
            if (c < 512) {
                int row = c >> 2, kc = c & 3;
                int m = m0 + row;
                long ar = 0;
                if (m < mEnd) ar = perm ? perm[m] : m; else sz = 0;
                src = A + ar*lda + k0 + kc*8;
                dst = sb + (row*KS + kc*8)*2;
            } else {
                int row = (c - 512) >> 2, kc = c & 3;
                src = W + (long)(n0 + row)*K + k0 + kc*8;
                dst = sb + (128*KS + row*KS + kc*8)*2;
            }
            cpa16p(dst, src, sz);
        }
        CP_COMMIT();
    };

    load_tile(0, 0); load_tile(1, 1);
    for (int kt = 0; kt < KT; kt++) {
        if (kt + 1 < KT) { CP_WAIT1(); } else { CP_WAIT0(); }
        __syncthreads();
        if (kt + 2 < KT) load_tile(kt + 2, (kt + 2) % 3);
        uint32_t sA = sbase + (kt % 3)*stageE*2;
        tile_mma_ldm<4,4>(sA, sA + 128*KS*2, mBase, nBase, lane, acc);
    }

#pragma unroll
    for (int mf = 0; mf < 4; mf++) {
#pragma unroll
        for (int half = 0; half < 2; half++) {
            int m = m0 + mBase + mf*16 + lq + half*8;
            if (m >= mEnd) continue;
#pragma unroll
            for (int nf = 0; nf < 4; nf++) {
                int n = n0 + nBase + nf*8 + lr*2;
                float x0 = (half ? acc[mf][nf].z : acc[mf][nf].x) + bias[n];
                float x1 = (half ? acc[mf][nf].w : acc[mf][nf].y) + bias[n+1];
                if (relu) { x0 = fmaxf(x0, 0.f); x1 = fmaxf(x1, 0.f); }
                if (Cb) {
                    *(uint32_t*)(Cb + (long)m*ldc + n) = pack_bf2(x0, x1);
                } else {
                    float2 v; v.x = x0; v.y = x1;
                    *(float2*)(Cf + (long)m*ldc + n) = v;
                }
            }
        }
    }
}

// ---------------------------------------------------------------------------
// Task sort / compaction (g_counts self-zeroes: consumed by scatter)
// ---------------------------------------------------------------------------
__global__ void sort_count_k(const int* __restrict__ task) {
    int b = blockIdx.x * blockDim.x + threadIdx.x;
    if (b < BB) atomicAdd(&g_counts[task[b]], 1);
}
__global__ void sort_off_k() {
    if (threadIdx.x == 0 && blockIdx.x == 0) {
        int off = 0;
        for (int t = 0; t < 8; t++) { g_off[t] = off; off += g_counts[t]; }
        g_off[8] = off;
        int idx = 0;
        for (int g = 0; g < 4; g++) {
            int s = g_off[g];
            int e = (g < 3) ? g_off[g+1] : BB;
            for (int m0 = s; m0 < e; m0 += 128) {
                g_tileG[idx] = g; g_tileM0[idx] = m0; g_tileE[idx] = e; idx++;
            }
        }
        g_nGru[0] = idx;
        idx = 0;
        for (int t = 0; t < 8; t++) {
            int s = g_off[t], e = g_off[t+1];
            for (int m0 = s; m0 < e; m0 += 128) {
                g_tileT[idx] = t; g_tileM0a[idx] = m0; g_tileEa[idx] = e; idx++;
            }
        }
        g_nAd[0] = idx;
    }
}
__global__ void sort_scatter_k(const int* __restrict__ task) {
    int b = blockIdx.x * blockDim.x + threadIdx.x;
    if (b < BB) {
        int t = task[b];
        int r = atomicSub(&g_counts[t], 1) - 1;   // consumes counts -> zero
        int p = g_off[t] + r;
        g_perm[p] = b;
        g_rowTask[p] = t;
    }
}

// ---------------------------------------------------------------------------
// GRU elementwise (h0 = 0):  lat2 = (1 - z) * tanh(nx + r*nh)
// ---------------------------------------------------------------------------
__global__ void gru_elem_k(const float* __restrict__ b_hh) {
    int p = blockIdx.x, h = threadIdx.x;
    int t = g_rowTask[p];
    int g = (t < 3) ? t : 3;
    const float* gxr = g_gx + (long)p*G3H;
    const float* bh  = b_hh + g*G3H;
    float r = 1.f / (1.f + expf(-(gxr[h]        + bh[h])));
    float z = 1.f / (1.f + expf(-(gxr[512 + h]  + bh[512 + h])));
    float n = tanhf(gxr[1024 + h] + r * bh[1024 + h]);
    g_lat2[(long)p*HH + h] = __float2bfloat16((1.f - z) * n);
}

// ---------------------------------------------------------------------------
// Heads: 7 logits + value per sample, scattered to original order
// ---------------------------------------------------------------------------
__global__ void heads_k(const float* __restrict__ Wh, const float* __restrict__ bh2,
                        const float* __restrict__ vw, const float* __restrict__ vb,
                        float* __restrict__ out) {
    int p = blockIdx.x * 8 + (threadIdx.x >> 5);
    int lane = threadIdx.x & 31;
    if (p >= BB) return;
    int t = g_rowTask[p];
    int borig = g_perm[p];
    const float* lrow = g_lat3 + (long)p*HH;
    const float* wt = Wh + t*7*HH;
    float acc[8];
#pragma unroll
    for (int a = 0; a < 8; a++) acc[a] = 0.f;
    for (int h = lane; h < HH; h += 32) {
        float x = lrow[h];
#pragma unroll
        for (int a = 0; a < 7; a++) acc[a] += x * wt[a*HH + h];
        acc[7] += x * vw[h];
    }
#pragma unroll
    for (int a = 0; a < 8; a++)
#pragma unroll
        for (int off = 16; off; off >>= 1)
            acc[a] += __shfl_down_sync(0xffffffff, acc[a], off);
    if (lane == 0) {
#pragma unroll
        for (int a = 0; a < 7; a++) out[borig*7 + a] = acc[a] + bh2[t*7 + a];
        out[BB*7 + borig] = acc[7] + vb[0];
    }
}

// ---------------------------------------------------------------------------
// Launch
// ---------------------------------------------------------------------------
extern "C" void kernel_launch(void* const* d_in, const int* in_sizes, int n_in,
                              void* d_out, int out_size) {
    const int*   obj   = (const int*)  d_in[0];
    const int*   color = (const int*)  d_in[1];
    const int*   state = (const int*)  d_in[2];
    const int*   dir   = (const int*)  d_in[3];
    const int*   task  = (const int*)  d_in[4];
    const float* eo    = (const float*)d_in[5];
    const float* ec    = (const float*)d_in[6];
    const float* es    = (const float*)d_in[7];
    const float* ed    = (const float*)d_in[8];
    const float* et    = (const float*)d_in[9];
    const float* c1w   = (const float*)d_in[10];
    const float* c1b   = (const float*)d_in[11];
    const float* c2w   = (const float*)d_in[12];
    const float* c2b   = (const float*)d_in[13];
    const float* prew  = (const float*)d_in[14];
    const float* preb  = (const float*)d_in[15];
    const float* W_ih  = (const float*)d_in[16];
    const float* b_ih  = (const float*)d_in[18];
    const float* b_hh  = (const float*)d_in[19];
    const float* Wa    = (const float*)d_in[20];
    const float* ba    = (const float*)d_in[21];
    const float* Wh    = (const float*)d_in[22];
    const float* bh2   = (const float*)d_in[23];
    const float* vw    = (const float*)d_in[24];
    const float* vb    = (const float*)d_in[25];
    float* out = (float*)d_out;

    bf *p_fused, *p_preW, *p_lat, *p_lat2, *p_Wih, *p_Wa;
    float *p_gx, *p_lat3;
    int *p_perm, *p_tG, *p_tM0, *p_tE, *p_nG, *p_tT, *p_tM0a, *p_tEa, *p_nA;
    cudaGetSymbolAddress((void**)&p_fused, g_fused);
    cudaGetSymbolAddress((void**)&p_preW,  g_preW);
    cudaGetSymbolAddress((void**)&p_lat,   g_lat);
    cudaGetSymbolAddress((void**)&p_gx,    g_gx);
    cudaGetSymbolAddress((void**)&p_lat2,  g_lat2);
    cudaGetSymbolAddress((void**)&p_lat3,  g_lat3);
    cudaGetSymbolAddress((void**)&p_Wih,   g_Wih);
    cudaGetSymbolAddress((void**)&p_Wa,    g_Wa);
    cudaGetSymbolAddress((void**)&p_perm,  g_perm);
    cudaGetSymbolAddress((void**)&p_tG,    g_tileG);
    cudaGetSymbolAddress((void**)&p_tM0,   g_tileM0);
    cudaGetSymbolAddress((void**)&p_tE,    g_tileE);
    cudaGetSymbolAddress((void**)&p_nG,    g_nGru);
    cudaGetSymbolAddress((void**)&p_tT,    g_tileT);
    cudaGetSymbolAddress((void**)&p_tM0a,  g_tileM0a);
    cudaGetSymbolAddress((void**)&p_tEa,   g_tileEa);
    cudaGetSymbolAddress((void**)&p_nA,    g_nAd);

    // weight re-layouts / conversions (f32 -> bf16)
    reorder_w1_k <<<216, 256>>>(c1w);
    reorder_w2_k <<<288, 256>>>(c2w);
    reorder_pre_k<<<512, 256>>>(prew);
    cvt_w_k<<<(N4_WIH + N4_WA + 255)/256, 256>>>(W_ih, Wa);

    // embedding gathers
    embed_k<<<37632, 256>>>(obj, color, state, eo, ec, es);
    tail_k <<<768,   256>>>(dir, task, ed, et);

    // dynamic smem: 3 stages
    const int smem1 = 3 * (128 + 64)  * KS * 2;   // 46080
    const int smem2 = 3 * (128 + 128) * KS * 2;   // 61440
    cudaFuncSetAttribute(conv1_k, cudaFuncAttributeMaxDynamicSharedMemorySize, smem1);
    cudaFuncSetAttribute(conv2_k, cudaFuncAttributeMaxDynamicSharedMemorySize, smem2);
    cudaFuncSetAttribute(gemm_bf, cudaFuncAttributeMaxDynamicSharedMemorySize, smem2);

    // convs (implicit GEMM, bf16 mma + ldmatrix + 3-stage cp.async)
    conv1_k<<<3136, 256, smem1>>>(c1b);
    conv2_k<<<3136, 256, smem2>>>(c2b);

    // pre-linear: M=8192, N=512, K=6368, relu, bf16 out
    gemm_bf<<<dim3(64, 4), 256, smem2>>>(p_fused, FUSED, nullptr,
                                  p_preW, 0, preb, 0,
                                  nullptr, p_lat, HH, FUSED, 1, BB,
                                  nullptr, nullptr, nullptr, nullptr);

    // task sort (counts self-zero via scatter's atomicSub)
    sort_count_k  <<<32, 256>>>(task);
    sort_off_k    <<<1,  1>>>();
    sort_scatter_k<<<32, 256>>>(task);

    // GRU gates: grouped (4 GRUs), perm gather; N=1536, K=512, f32 out
    gemm_bf<<<dim3(80, 12), 256, smem2>>>(p_lat, HH, p_perm,
                                   p_Wih, (long long)G3H*HH, b_ih, G3H,
                                   p_gx, nullptr, G3H, HH, 0, 0,
                                   p_tG, p_tM0, p_tE, p_nG);
    gru_elem_k<<<BB, HH>>>(b_hh);

    // adapter: grouped (8 tasks); N=512, K=512, relu, f32 out
    gemm_bf<<<dim3(80, 4), 256, smem2>>>(p_lat2, HH, nullptr,
                                  p_Wa, (long long)HH*HH, ba, HH,
                                  p_lat3, nullptr, HH, HH, 1, 0,
                                  p_tT, p_tM0a, p_tEa, p_nA);

    // policy heads + value
    heads_k<<<1024, 256>>>(Wh, bh2, vw, vb, out);
}

// round 14
// speedup vs baseline: 1.0495x; 1.0257x over previous
#include <cuda_runtime.h>
#include <cuda_bf16.h>
#include <math.h>
#include <stdint.h>

// ---------------------------------------------------------------------------
// Problem constants
// ---------------------------------------------------------------------------
#define BB     8192
#define NPOS   49
#define MCONV  (BB*NPOS)        // 401408
#define CI1    96
#define CO1    64
#define K1     (9*CI1)          // 864
#define CI2    64
#define CO2    128
#define K2     (9*CI2)          // 576
#define FUSED  6368
#define HH     512
#define G3H    1536
#define KS     40               // smem k-stride in bf16 (80B rows -> conflict-free)

typedef __nv_bfloat16 bf;

// ---------------------------------------------------------------------------
// Scratch (__device__ globals; zero-init at module load -> free SAME padding)
// ---------------------------------------------------------------------------
__device__ __align__(16) bf    g_xpad [BB*81*CI1];
__device__ __align__(16) bf    g_y1pad[BB*81*CI2];
__device__ __align__(16) bf    g_fused[BB*FUSED];
__device__ __align__(16) bf    g_W1re [CO1*K1];
__device__ __align__(16) bf    g_W2re [CO2*K2];
__device__ __align__(16) bf    g_preW [HH*FUSED];
__device__ __align__(16) bf    g_Wih  [4*G3H*HH];
__device__ __align__(16) bf    g_Wa   [8*HH*HH];
__device__ __align__(16) bf    g_lat  [BB*HH];
__device__ __align__(16) float g_gx   [BB*G3H];
__device__ __align__(16) bf    g_lat2 [BB*HH];
__device__ __align__(16) float g_lat3 [BB*HH];
__device__ int g_perm[BB], g_rowTask[BB];
__device__ int g_counts[8], g_off[9];
__device__ int g_tileG [80], g_tileM0 [80], g_tileE [80], g_nGru[1];
__device__ int g_tileT [80], g_tileM0a[80], g_tileEa[80], g_nAd[1];

// ---------------------------------------------------------------------------
// Helpers
// ---------------------------------------------------------------------------
__device__ __forceinline__ uint32_t pack_bf2(float lo, float hi) {
    __nv_bfloat162 p = __floats2bfloat162_rn(lo, hi);
    return *reinterpret_cast<uint32_t*>(&p);
}
__device__ __forceinline__ void cpa16(uint32_t dst, const void* src) {
    asm volatile("cp.async.cg.shared.global [%0], [%1], 16;\n"
                 :: "r"(dst), "l"(src));
}
__device__ __forceinline__ void cpa16p(uint32_t dst, const void* src, int sz) {
    asm volatile("cp.async.cg.shared.global [%0], [%1], 16, %2;\n"
                 :: "r"(dst), "l"(src), "r"(sz));
}
#define CP_COMMIT() asm volatile("cp.async.commit_group;\n" ::: "memory")
#define CP_WAIT0()  asm volatile("cp.async.wait_group 0;\n" ::: "memory")
#define CP_WAIT1()  asm volatile("cp.async.wait_group 1;\n" ::: "memory")

__device__ __forceinline__ void mma_bf16(float4& d,
    uint32_t a0, uint32_t a1, uint32_t a2, uint32_t a3,
    uint32_t b0, uint32_t b1)
{
    asm volatile(
        "mma.sync.aligned.m16n8k16.row.col.f32.bf16.bf16.f32 "
        "{%0,%1,%2,%3}, {%4,%5,%6,%7}, {%8,%9}, {%0,%1,%2,%3};\n"
        : "+f"(d.x), "+f"(d.y), "+f"(d.z), "+f"(d.w)
        : "r"(a0), "r"(a1), "r"(a2), "r"(a3), "r"(b0), "r"(b1));
}
__device__ __forceinline__ void ldm_x4(uint32_t (&r)[4], uint32_t addr) {
    asm volatile("ldmatrix.sync.aligned.m8n8.x4.shared.b16 {%0,%1,%2,%3}, [%4];"
                 : "=r"(r[0]), "=r"(r[1]), "=r"(r[2]), "=r"(r[3]) : "r"(addr));
}

// One k32 tile of MMAs over MF*16 x NF*8 warp tile, ldmatrix fragment loads.
template<int MF, int NF>
__device__ __forceinline__ void tile_mma_ldm(
    uint32_t sA, uint32_t sB, int mBase, int nBase, int lane,
    float4 (&acc)[MF][NF])
{
    int la = lane & 15, ka = lane >> 4;                 // A: row-in-16, k-half
    int nb = (lane & 7) + ((lane >> 4) << 3);           // B: n-row
    int kb = (lane >> 3) & 1;                           // B: k-half
#pragma unroll
    for (int ks = 0; ks < 2; ks++) {
        uint32_t b[NF][2];
#pragma unroll
        for (int p = 0; p < NF/2; p++) {
            uint32_t r[4];
            ldm_x4(r, sB + ((nBase + p*16 + nb)*KS + ks*16 + kb*8)*2);
            b[2*p  ][0] = r[0]; b[2*p  ][1] = r[1];
            b[2*p+1][0] = r[2]; b[2*p+1][1] = r[3];
        }
#pragma unroll
        for (int mf = 0; mf < MF; mf++) {
            uint32_t a[4];
            ldm_x4(a, sA + ((mBase + mf*16 + la)*KS + ks*16 + ka*8)*2);
#pragma unroll
            for (int nf = 0; nf < NF; nf++)
                mma_bf16(acc[mf][nf], a[0], a[1], a[2], a[3],
                         b[nf][0], b[nf][1]);
        }
    }
}

// ---------------------------------------------------------------------------
// Weight re-layout / conversion kernels
// ---------------------------------------------------------------------------
__global__ void reorder_w1_k(const float* __restrict__ w) {
    int idx = blockIdx.x * blockDim.x + threadIdx.x;
    int n = idx / K1, k = idx % K1;
    int t = k / CI1, i = k % CI1;
    g_W1re[idx] = __float2bfloat16(w[(n*CI1 + i)*9 + t]);
}
__global__ void reorder_w2_k(const float* __restrict__ w) {
    int idx = blockIdx.x * blockDim.x + threadIdx.x;
    int n = idx / K2, k = idx % K2;
    int t = k / CI2, i = k % CI2;
    g_W2re[idx] = __float2bfloat16(w[(n*CI2 + i)*9 + t]);
}
// one block per output row n: stage the row in smem, both sides coalesced
__global__ __launch_bounds__(256) void reorder_pre_k(const float* __restrict__ w) {
    __shared__ float buf[FUSED];
    int n = blockIdx.x;
    for (int k = threadIdx.x; k < FUSED; k += 256) buf[k] = w[n*FUSED + k];
    __syncthreads();
    for (int k = threadIdx.x; k < FUSED; k += 256) {
        int src;
        if (k < 6272) { int pos = k >> 7, ch = k & 127; src = ch*49 + pos; }
        else src = k;
        g_preW[n*FUSED + k] = __float2bfloat16(buf[src]);
    }
}
// one launch converting both W_ih (4*G3H*HH) and Wa (8*HH*HH) to bf16
#define N4_WIH (4*G3H*HH/4)
#define N4_WA  (8*HH*HH/4)
__global__ void cvt_w_k(const float* __restrict__ wih, const float* __restrict__ wa) {
    int i = blockIdx.x * blockDim.x + threadIdx.x;
    const float* src; bf* dst;
    if (i < N4_WIH) { src = wih + i*4; dst = g_Wih + i*4; }
    else {
        int j = i - N4_WIH;
        if (j >= N4_WA) return;
        src = wa + j*4; dst = g_Wa + j*4;
    }
    float4 v = *(const float4*)src;
    uint2 o; o.x = pack_bf2(v.x, v.y); o.y = pack_bf2(v.z, v.w);
    *(uint2*)dst = o;
}

// ---------------------------------------------------------------------------
// Embedding gather -> padded activation [B][9*9][96] bf16, 16B stores
// ---------------------------------------------------------------------------
__global__ void embed_k(const int* __restrict__ obj, const int* __restrict__ col,
                        const int* __restrict__ sta,
                        const float* __restrict__ eo, const float* __restrict__ ec,
                        const float* __restrict__ es) {
    long idx = (long)blockIdx.x * blockDim.x + threadIdx.x;   // MCONV*12
    int sub = (int)(idx % 12);
    long cell = idx / 12;
    int b = (int)(cell / 49), pos = (int)(cell % 49);
    int r = pos / 7, c = pos % 7;
    int tbl = sub >> 2, j = sub & 3;
    int e; const float* tab;
    if (tbl == 0)      { e = obj[cell]; tab = eo; }
    else if (tbl == 1) { e = col[cell]; tab = ec; }
    else               { e = sta[cell]; tab = es; }
    float4 v0 = *(const float4*)(tab + e*32 + j*8);
    float4 v1 = *(const float4*)(tab + e*32 + j*8 + 4);
    uint4 o;
    o.x = pack_bf2(v0.x, v0.y); o.y = pack_bf2(v0.z, v0.w);
    o.z = pack_bf2(v1.x, v1.y); o.w = pack_bf2(v1.z, v1.w);
    *(uint4*)(g_xpad + ((long)(b*81 + (r+1)*9 + (c+1)))*CI1 + tbl*32 + j*8) = o;
}

__global__ void tail_k(const int* __restrict__ dir, const int* __restrict__ task,
                       const float* __restrict__ ed, const float* __restrict__ et) {
    int idx = blockIdx.x * blockDim.x + threadIdx.x;
    int b = idx / 24, sub = idx % 24;
    float4 v; int dst;
    if (sub < 8) { v = *(const float4*)(ed + dir[b]*32 + sub*4);  dst = 6272 + sub*4; }
    else { int j = sub - 8; v = *(const float4*)(et + task[b]*64 + j*4); dst = 6304 + j*4; }
    uint2 o; o.x = pack_bf2(v.x, v.y); o.y = pack_bf2(v.z, v.w);
    *(uint2*)(g_fused + (long)b*FUSED + dst) = o;
}

// ---------------------------------------------------------------------------
// conv1: implicit GEMM  M=401408, N=64, K=864 -> relu -> y1pad interior
// CTA 128x64, 8 warps (4x2), warp tile 32x32; 3-stage cp.async, 1 sync/tile
// ---------------------------------------------------------------------------
__global__ __launch_bounds__(256) void conv1_k(const float* __restrict__ bias) {
    extern __shared__ __align__(16) bf smem1[];
    const int stageE = (128 + 64)*KS;          // bf16 elements per stage
    int m0 = blockIdx.x * 128;
    int tid = threadIdx.x;
    int warp = tid >> 5, lane = tid & 31;
    int lq = lane >> 2, lr = lane & 3;
    int mBase = (warp >> 1) * 32, nBase = (warp & 1) * 32;
    uint32_t sbase = (uint32_t)__cvta_generic_to_shared(smem1);

    float4 acc[2][4];
#pragma unroll
    for (int i = 0; i < 2; i++)
#pragma unroll
        for (int j = 0; j < 4; j++) acc[i][j] = make_float4(0.f,0.f,0.f,0.f);

    const int KT = K1/32;                       // 27
    auto load_tile = [&](int kt, int buf) {
        int k0 = kt*32;
        int tap = k0 / CI1;
        int i0  = k0 - tap*CI1;
        int offp = ((tap/3)*9 + (tap%3)) * CI1;
        uint32_t sb = sbase + buf*stageE*2;
#pragma unroll
        for (int it = 0; it < 3; it++) {
            int c = tid + it*256;               // 768 16B chunks
            const bf* src; uint32_t dst;
            if (c < 512) {
                int row = c >> 2, kc = c & 3;
                int m = m0 + row;
                int b = m/49, pos = m%49, r = pos/7, cc = pos%7;
                src = g_xpad + (long)(b*81 + r*9 + cc)*CI1 + offp + i0 + kc*8;
                dst = sb + (row*KS + kc*8)*2;
            } else {
                int row = (c - 512) >> 2, kc = c & 3;
                src = g_W1re + row*K1 + k0 + kc*8;
                dst = sb + (128*KS + row*KS + kc*8)*2;
            }
            cpa16(dst, src);
        }
        CP_COMMIT();
    };

    load_tile(0, 0); load_tile(1, 1);
    for (int kt = 0; kt < KT; kt++) {
        if (kt + 1 < KT) { CP_WAIT1(); } else { CP_WAIT0(); }
        __syncthreads();
        if (kt + 2 < KT) load_tile(kt + 2, (kt + 2) % 3);
        uint32_t sA = sbase + (kt % 3)*stageE*2;
        tile_mma_ldm<2,4>(sA, sA + 128*KS*2, mBase, nBase, lane, acc);
    }

#pragma unroll
    for (int mf = 0; mf < 2; mf++) {
#pragma unroll
        for (int half = 0; half < 2; half++) {
            int m = m0 + mBase + mf*16 + lq + half*8;
            int b = m/49, pos = m%49, r = pos/7, c = pos%7;
            bf* dst = g_y1pad + (long)(b*81 + (r+1)*9 + (c+1)) * CI2;
#pragma unroll
            for (int nf = 0; nf < 4; nf++) {
                int n = nBase + nf*8 + lr*2;
                float x0 = (half ? acc[mf][nf].z : acc[mf][nf].x) + bias[n];
                float x1 = (half ? acc[mf][nf].w : acc[mf][nf].y) + bias[n+1];
                *(uint32_t*)(dst + n) = pack_bf2(fmaxf(x0,0.f), fmaxf(x1,0.f));
            }
        }
    }
}

// ---------------------------------------------------------------------------
// conv2: implicit GEMM  M=401408, N=128, K=576 -> relu -> fused[pos*128+ch]
// CTA 128x128, 8 warps (2x4), warp tile 64x32; 3-stage, 1 sync/tile
// ---------------------------------------------------------------------------
__global__ __launch_bounds__(256) void conv2_k(const float* __restrict__ bias) {
    extern __shared__ __align__(16) bf smem2[];
    const int stageE = (128 + 128)*KS;
    int m0 = blockIdx.x * 128;
    int tid = threadIdx.x;
    int warp = tid >> 5, lane = tid & 31;
    int lq = lane >> 2, lr = lane & 3;
    int mBase = (warp >> 2) * 64, nBase = (warp & 3) * 32;
    uint32_t sbase = (uint32_t)__cvta_generic_to_shared(smem2);

    float4 acc[4][4];
#pragma unroll
    for (int i = 0; i < 4; i++)
#pragma unroll
        for (int j = 0; j < 4; j++) acc[i][j] = make_float4(0.f,0.f,0.f,0.f);

    const int KT = K2/32;                       // 18
    auto load_tile = [&](int kt, int buf) {
        int k0 = kt*32;
        int tap = k0 / CI2;
        int i0  = k0 - tap*CI2;
        int offp = ((tap/3)*9 + (tap%3)) * CI2;
        uint32_t sb = sbase + buf*stageE*2;
#pragma unroll
        for (int it = 0; it < 4; it++) {
            int c = tid + it*256;               // 1024 16B chunks
            const bf* src; uint32_t dst;
            if (c < 512) {
                int row = c >> 2, kc = c & 3;
                int m = m0 + row;
                int b = m/49, pos = m%49, r = pos/7, cc = pos%7;
                src = g_y1pad + (long)(b*81 + r*9 + cc)*CI2 + offp + i0 + kc*8;
                dst = sb + (row*KS + kc*8)*2;
            } else {
                int row = (c - 512) >> 2, kc = c & 3;
                src = g_W2re + row*K2 + k0 + kc*8;
                dst = sb + (128*KS + row*KS + kc*8)*2;
            }
            cpa16(dst, src);
        }
        CP_COMMIT();
    };

    load_tile(0, 0); load_tile(1, 1);
    for (int kt = 0; kt < KT; kt++) {
        if (kt + 1 < KT) { CP_WAIT1(); } else { CP_WAIT0(); }
        __syncthreads();
        if (kt + 2 < KT) load_tile(kt + 2, (kt + 2) % 3);
        uint32_t sA = sbase + (kt % 3)*stageE*2;
        tile_mma_ldm<4,4>(sA, sA + 128*KS*2, mBase, nBase, lane, acc);
    }

#pragma unroll
    for (int mf = 0; mf < 4; mf++) {
#pragma unroll
        for (int half = 0; half < 2; half++) {
            int m = m0 + mBase + mf*16 + lq + half*8;
            int b = m/49, pos = m%49;
            bf* dst = g_fused + (long)b*FUSED + pos*128;
#pragma unroll
            for (int nf = 0; nf < 4; nf++) {
                int n = nBase + nf*8 + lr*2;
                float x0 = (half ? acc[mf][nf].z : acc[mf][nf].x) + bias[n];
                float x1 = (half ? acc[mf][nf].w : acc[mf][nf].y) + bias[n+1];
                *(uint32_t*)(dst + n) = pack_bf2(fmaxf(x0,0.f), fmaxf(x1,0.f));
            }
        }
    }
}

// ---------------------------------------------------------------------------
// Generic TN GEMM (bf16 MMA, 3-stage cp.async, ldmatrix):
// C[m,n] = act( sum_k A[m,k]*W[n,k] + bias[n] ); optional perm gather,
// grouped M-tiles; output f32 (Cf) or bf16 (Cb).  CTA 128x128.
// ---------------------------------------------------------------------------
__global__ __launch_bounds__(256) void gemm_bf(
    const bf* __restrict__ A, int lda,
    const int* __restrict__ perm,
    const bf* __restrict__ Wg, long long wStride,
    const float* __restrict__ biasg, int biasStride,
    float* __restrict__ Cf, bf* __restrict__ Cb, int ldc,
    int K, int relu, int denseM,
    const int* __restrict__ tileG, const int* __restrict__ tileM0,
    const int* __restrict__ tileE, const int* __restrict__ nTilesPtr)
{
    extern __shared__ __align__(16) bf smemg[];
    const int stageE = (128 + 128)*KS;
    int m0, mEnd, g;
    if (tileG) {
        int t = blockIdx.x;
        if (t >= *nTilesPtr) return;
        g = tileG[t]; m0 = tileM0[t]; mEnd = tileE[t];
    } else {
        g = 0; m0 = blockIdx.x * 128; mEnd = denseM;
    }
    const bf* W = Wg + (long long)g * wStride;
    const float* bias = biasg + g * biasStride;
    int n0 = blockIdx.y * 128;

    int tid = threadIdx.x;
    int warp = tid >> 5, lane = tid & 31;
    int lq = lane >> 2, lr = lane & 3;
    int mBase = (warp >> 2) * 64, nBase = (warp & 3) * 32;
    uint32_t sbase = (uint32_t)__cvta_generic_to_shared(smemg);

    float4 acc[4][4];
#pragma unroll
    for (int i = 0; i < 4; i++)
#pragma unroll
        for (int j = 0; j < 4; j++) acc[i][j] = make_float4(0.f,0.f,0.f,0.f);

    const int KT = K/32;
    auto load_tile = [&](int kt, int buf) {
        int k0 = kt*32;
        uint32_t sb = sbase + buf*stageE*2;
#pragma unroll
        for (int it = 0; it < 4; it++) {
            int c = tid + it*256;
            const bf* src; uint32_t dst; int sz = 16;
            if (c < 512) {
                int row = c >> 2, kc = c & 3;
                int m = m0 + row;
                long ar = 0;
                if (m < mEnd) ar = perm ? perm[m] : m; else sz = 0;
                src = A + ar*lda + k0 + kc*8;
                dst = sb + (row*KS + kc*8)*2;
            } else {
                int row = (c - 512) >> 2, kc = c & 3;
                src = W + (long)(n0 + row)*K + k0 + kc*8;
                dst = sb + (128*KS + row*KS + kc*8)*2;
            }
            cpa16p(dst, src, sz);
        }
        CP_COMMIT();
    };

    load_tile(0, 0); load_tile(1, 1);
    for (int kt = 0; kt < KT; kt++) {
        if (kt + 1 < KT) { CP_WAIT1(); } else { CP_WAIT0(); }
        __syncthreads();
        if (kt + 2 < KT) load_tile(kt + 2, (kt + 2) % 3);
        uint32_t sA = sbase + (kt % 3)*stageE*2;
        tile_mma_ldm<4,4>(sA, sA + 128*KS*2, mBase, nBase, lane, acc);
    }

#pragma unroll
    for (int mf = 0; mf < 4; mf++) {
#pragma unroll
        for (int half = 0; half < 2; half++) {
            int m = m0 + mBase + mf*16 + lq + half*8;
            if (m >= mEnd) continue;
#pragma unroll
            for (int nf = 0; nf < 4; nf++) {
                int n = n0 + nBase + nf*8 + lr*2;
                float x0 = (half ? acc[mf][nf].z : acc[mf][nf].x) + bias[n];
                float x1 = (half ? acc[mf][nf].w : acc[mf][nf].y) + bias[n+1];
                if (relu) { x0 = fmaxf(x0, 0.f); x1 = fmaxf(x1, 0.f); }
                if (Cb) {
                    *(uint32_t*)(Cb + (long)m*ldc + n) = pack_bf2(x0, x1);
                } else {
                    float2 v; v.x = x0; v.y = x1;
                    *(float2*)(Cf + (long)m*ldc + n) = v;
                }
            }
        }
    }
}

// ---------------------------------------------------------------------------
// Task sort / compaction (g_counts self-zeroes: consumed by scatter)
// ---------------------------------------------------------------------------
__global__ void sort_count_k(const int* __restrict__ task) {
    int b = blockIdx.x * blockDim.x + threadIdx.x;
    if (b < BB) atomicAdd(&g_counts[task[b]], 1);
}
__global__ void sort_off_k() {
    if (threadIdx.x == 0 && blockIdx.x == 0) {
        int off = 0;
        for (int t = 0; t < 8; t++) { g_off[t] = off; off += g_counts[t]; }
        g_off[8] = off;
        int idx = 0;
        for (int g = 0; g < 4; g++) {
            int s = g_off[g];
            int e = (g < 3) ? g_off[g+1] : BB;
            for (int m0 = s; m0 < e; m0 += 128) {
                g_tileG[idx] = g; g_tileM0[idx] = m0; g_tileE[idx] = e; idx++;
            }
        }
        g_nGru[0] = idx;
        idx = 0;
        for (int t = 0; t < 8; t++) {
            int s = g_off[t], e = g_off[t+1];
            for (int m0 = s; m0 < e; m0 += 128) {
                g_tileT[idx] = t; g_tileM0a[idx] = m0; g_tileEa[idx] = e; idx++;
            }
        }
        g_nAd[0] = idx;
    }
}
__global__ void sort_scatter_k(const int* __restrict__ task) {
    int b = blockIdx.x * blockDim.x + threadIdx.x;
    if (b < BB) {
        int t = task[b];
        int r = atomicSub(&g_counts[t], 1) - 1;   // consumes counts -> zero
        int p = g_off[t] + r;
        g_perm[p] = b;
        g_rowTask[p] = t;
    }
}

// ---------------------------------------------------------------------------
// GRU elementwise (h0 = 0):  lat2 = (1 - z) * tanh(nx + r*nh)
// ---------------------------------------------------------------------------
__global__ void gru_elem_k(const float* __restrict__ b_hh) {
    int p = blockIdx.x, h = threadIdx.x;
    int t = g_rowTask[p];
    int g = (t < 3) ? t : 3;
    const float* gxr = g_gx + (long)p*G3H;
    const float* bh  = b_hh + g*G3H;
    float r = 1.f / (1.f + expf(-(gxr[h]        + bh[h])));
    float z = 1.f / (1.f + expf(-(gxr[512 + h]  + bh[512 + h])));
    float n = tanhf(gxr[1024 + h] + r * bh[1024 + h]);
    g_lat2[(long)p*HH + h] = __float2bfloat16((1.f - z) * n);
}

// ---------------------------------------------------------------------------
// Heads: 7 logits + value per sample, scattered to original order
// ---------------------------------------------------------------------------
__global__ void heads_k(const float* __restrict__ Wh, const float* __restrict__ bh2,
                        const float* __restrict__ vw, const float* __restrict__ vb,
                        float* __restrict__ out) {
    int p = blockIdx.x * 8 + (threadIdx.x >> 5);
    int lane = threadIdx.x & 31;
    if (p >= BB) return;
    int t = g_rowTask[p];
    int borig = g_perm[p];
    const float* lrow = g_lat3 + (long)p*HH;
    const float* wt = Wh + t*7*HH;
    float acc[8];
#pragma unroll
    for (int a = 0; a < 8; a++) acc[a] = 0.f;
    for (int h = lane; h < HH; h += 32) {
        float x = lrow[h];
#pragma unroll
        for (int a = 0; a < 7; a++) acc[a] += x * wt[a*HH + h];
        acc[7] += x * vw[h];
    }
#pragma unroll
    for (int a = 0; a < 8; a++)
#pragma unroll
        for (int off = 16; off; off >>= 1)
            acc[a] += __shfl_down_sync(0xffffffff, acc[a], off);
    if (lane == 0) {
#pragma unroll
        for (int a = 0; a < 7; a++) out[borig*7 + a] = acc[a] + bh2[t*7 + a];
        out[BB*7 + borig] = acc[7] + vb[0];
    }
}

// ---------------------------------------------------------------------------
// Launch
// ---------------------------------------------------------------------------
extern "C" void kernel_launch(void* const* d_in, const int* in_sizes, int n_in,
                              void* d_out, int out_size) {
    const int*   obj   = (const int*)  d_in[0];
    const int*   color = (const int*)  d_in[1];
    const int*   state = (const int*)  d_in[2];
    const int*   dir   = (const int*)  d_in[3];
    const int*   task  = (const int*)  d_in[4];
    const float* eo    = (const float*)d_in[5];
    const float* ec    = (const float*)d_in[6];
    const float* es    = (const float*)d_in[7];
    const float* ed    = (const float*)d_in[8];
    const float* et    = (const float*)d_in[9];
    const float* c1w   = (const float*)d_in[10];
    const float* c1b   = (const float*)d_in[11];
    const float* c2w   = (const float*)d_in[12];
    const float* c2b   = (const float*)d_in[13];
    const float* prew  = (const float*)d_in[14];
    const float* preb  = (const float*)d_in[15];
    const float* W_ih  = (const float*)d_in[16];
    const float* b_ih  = (const float*)d_in[18];
    const float* b_hh  = (const float*)d_in[19];
    const float* Wa    = (const float*)d_in[20];
    const float* ba    = (const float*)d_in[21];
    const float* Wh    = (const float*)d_in[22];
    const float* bh2   = (const float*)d_in[23];
    const float* vw    = (const float*)d_in[24];
    const float* vb    = (const float*)d_in[25];
    float* out = (float*)d_out;

    bf *p_fused, *p_preW, *p_lat, *p_lat2, *p_Wih, *p_Wa;
    float *p_gx, *p_lat3;
    int *p_perm, *p_tG, *p_tM0, *p_tE, *p_nG, *p_tT, *p_tM0a, *p_tEa, *p_nA;
    cudaGetSymbolAddress((void**)&p_fused, g_fused);
    cudaGetSymbolAddress((void**)&p_preW,  g_preW);
    cudaGetSymbolAddress((void**)&p_lat,   g_lat);
    cudaGetSymbolAddress((void**)&p_gx,    g_gx);
    cudaGetSymbolAddress((void**)&p_lat2,  g_lat2);
    cudaGetSymbolAddress((void**)&p_lat3,  g_lat3);
    cudaGetSymbolAddress((void**)&p_Wih,   g_Wih);
    cudaGetSymbolAddress((void**)&p_Wa,    g_Wa);
    cudaGetSymbolAddress((void**)&p_perm,  g_perm);
    cudaGetSymbolAddress((void**)&p_tG,    g_tileG);
    cudaGetSymbolAddress((void**)&p_tM0,   g_tileM0);
    cudaGetSymbolAddress((void**)&p_tE,    g_tileE);
    cudaGetSymbolAddress((void**)&p_nG,    g_nGru);
    cudaGetSymbolAddress((void**)&p_tT,    g_tileT);
    cudaGetSymbolAddress((void**)&p_tM0a,  g_tileM0a);
    cudaGetSymbolAddress((void**)&p_tEa,   g_tileEa);
    cudaGetSymbolAddress((void**)&p_nA,    g_nAd);

    // weight re-layouts / conversions (f32 -> bf16)
    reorder_w1_k <<<216, 256>>>(c1w);
    reorder_w2_k <<<288, 256>>>(c2w);
    reorder_pre_k<<<512, 256>>>(prew);
    cvt_w_k<<<(N4_WIH + N4_WA + 255)/256, 256>>>(W_ih, Wa);

    // embedding gathers (16B stores)
    embed_k<<<18816, 256>>>(obj, color, state, eo, ec, es);
    tail_k <<<768,   256>>>(dir, task, ed, et);

    // dynamic smem: 3 stages
    const int smem1 = 3 * (128 + 64)  * KS * 2;   // 46080
    const int smem2 = 3 * (128 + 128) * KS * 2;   // 61440
    cudaFuncSetAttribute(conv1_k, cudaFuncAttributeMaxDynamicSharedMemorySize, smem1);
    cudaFuncSetAttribute(conv2_k, cudaFuncAttributeMaxDynamicSharedMemorySize, smem2);
    cudaFuncSetAttribute(gemm_bf, cudaFuncAttributeMaxDynamicSharedMemorySize, smem2);

    // convs (implicit GEMM, bf16 mma + ldmatrix + 3-stage cp.async)
    conv1_k<<<3136, 256, smem1>>>(c1b);
    conv2_k<<<3136, 256, smem2>>>(c2b);

    // pre-linear: M=8192, N=512, K=6368, relu, bf16 out
    gemm_bf<<<dim3(64, 4), 256, smem2>>>(p_fused, FUSED, nullptr,
                                  p_preW, 0, preb, 0,
                                  nullptr, p_lat, HH, FUSED, 1, BB,
                                  nullptr, nullptr, nullptr, nullptr);

    // task sort (counts self-zero via scatter's atomicSub)
    sort_count_k  <<<32, 256>>>(task);
    sort_off_k    <<<1,  1>>>();
    sort_scatter_k<<<32, 256>>>(task);

    // GRU gates: grouped (4 GRUs), perm gather; N=1536, K=512, f32 out
    gemm_bf<<<dim3(80, 12), 256, smem2>>>(p_lat, HH, p_perm,
                                   p_Wih, (long long)G3H*HH, b_ih, G3H,
                                   p_gx, nullptr, G3H, HH, 0, 0,
                                   p_tG, p_tM0, p_tE, p_nG);
    gru_elem_k<<<BB, HH>>>(b_hh);

    // adapter: grouped (8 tasks); N=512, K=512, relu, f32 out
    gemm_bf<<<dim3(80, 4), 256, smem2>>>(p_lat2, HH, nullptr,
                                  p_Wa, (long long)HH*HH, ba, HH,
                                  p_lat3, nullptr, HH, HH, 1, 0,
                                  p_tT, p_tM0a, p_tEa, p_nA);

    // policy heads + value
    heads_k<<<1024, 256>>>(Wh, bh2, vw, vb, out);
}

// round 16
// speedup vs baseline: 1.0681x; 1.0177x over previous
#include <cuda_runtime.h>
#include <cuda_bf16.h>
#include <math.h>
#include <stdint.h>

// ---------------------------------------------------------------------------
// Problem constants
// ---------------------------------------------------------------------------
#define BB     8192
#define NPOS   49
#define MCONV  (BB*NPOS)        // 401408
#define CI1    96
#define CO1    64
#define K1     (9*CI1)          // 864
#define CI2    64
#define CO2    128
#define K2     (9*CI2)          // 576
#define FUSED  6368
#define HH     512
#define G3H    1536
#define KS     40               // smem k-stride in bf16 (80B rows -> conflict-free)

typedef __nv_bfloat16 bf;

// ---------------------------------------------------------------------------
// Scratch (__device__ globals; zero-init at module load -> free SAME padding)
// ---------------------------------------------------------------------------
__device__ __align__(16) bf    g_xpad [BB*81*CI1];
__device__ __align__(16) bf    g_y1pad[BB*81*CI2];
__device__ __align__(16) bf    g_fused[BB*FUSED];
__device__ __align__(16) bf    g_W1re [CO1*K1];
__device__ __align__(16) bf    g_W2re [CO2*K2];
__device__ __align__(16) bf    g_preW [HH*FUSED];
__device__ __align__(16) bf    g_Wih  [4*G3H*HH];
__device__ __align__(16) bf    g_Wa   [8*HH*HH];
__device__ __align__(16) bf    g_lat  [BB*HH];
__device__ __align__(16) float g_gx   [BB*G3H];
__device__ __align__(16) bf    g_lat2 [BB*HH];
__device__ __align__(16) float g_lat3 [BB*HH];
__device__ int g_perm[BB], g_rowTask[BB];
__device__ int g_counts[8], g_off[9];
__device__ int g_tileG [80], g_tileM0 [80], g_tileE [80], g_nGru[1];
__device__ int g_tileT [80], g_tileM0a[80], g_tileEa[80], g_nAd[1];

// ---------------------------------------------------------------------------
// Helpers
// ---------------------------------------------------------------------------
__device__ __forceinline__ uint32_t pack_bf2(float lo, float hi) {
    __nv_bfloat162 p = __floats2bfloat162_rn(lo, hi);
    return *reinterpret_cast<uint32_t*>(&p);
}
__device__ __forceinline__ void cpa16(uint32_t dst, const void* src) {
    asm volatile("cp.async.cg.shared.global [%0], [%1], 16;\n"
                 :: "r"(dst), "l"(src));
}
__device__ __forceinline__ void cpa16p(uint32_t dst, const void* src, int sz) {
    asm volatile("cp.async.cg.shared.global [%0], [%1], 16, %2;\n"
                 :: "r"(dst), "l"(src), "r"(sz));
}
#define CP_COMMIT() asm volatile("cp.async.commit_group;\n" ::: "memory")
#define CP_WAIT0()  asm volatile("cp.async.wait_group 0;\n" ::: "memory")
#define CP_WAIT1()  asm volatile("cp.async.wait_group 1;\n" ::: "memory")

__device__ __forceinline__ void mma_bf16(float4& d,
    uint32_t a0, uint32_t a1, uint32_t a2, uint32_t a3,
    uint32_t b0, uint32_t b1)
{
    asm volatile(
        "mma.sync.aligned.m16n8k16.row.col.f32.bf16.bf16.f32 "
        "{%0,%1,%2,%3}, {%4,%5,%6,%7}, {%8,%9}, {%0,%1,%2,%3};\n"
        : "+f"(d.x), "+f"(d.y), "+f"(d.z), "+f"(d.w)
        : "r"(a0), "r"(a1), "r"(a2), "r"(a3), "r"(b0), "r"(b1));
}
__device__ __forceinline__ void ldm_x4(uint32_t (&r)[4], uint32_t addr) {
    asm volatile("ldmatrix.sync.aligned.m8n8.x4.shared.b16 {%0,%1,%2,%3}, [%4];"
                 : "=r"(r[0]), "=r"(r[1]), "=r"(r[2]), "=r"(r[3]) : "r"(addr));
}

// One k32 tile of MMAs over MF*16 x NF*8 warp tile, ldmatrix fragment loads.
template<int MF, int NF>
__device__ __forceinline__ void tile_mma_ldm(
    uint32_t sA, uint32_t sB, int mBase, int nBase, int lane,
    float4 (&acc)[MF][NF])
{
    int la = lane & 15, ka = lane >> 4;                 // A: row-in-16, k-half
    int nb = (lane & 7) + ((lane >> 4) << 3);           // B: n-row
    int kb = (lane >> 3) & 1;                           // B: k-half
#pragma unroll
    for (int ks = 0; ks < 2; ks++) {
        uint32_t b[NF][2];
#pragma unroll
        for (int p = 0; p < NF/2; p++) {
            uint32_t r[4];
            ldm_x4(r, sB + ((nBase + p*16 + nb)*KS + ks*16 + kb*8)*2);
            b[2*p  ][0] = r[0]; b[2*p  ][1] = r[1];
            b[2*p+1][0] = r[2]; b[2*p+1][1] = r[3];
        }
#pragma unroll
        for (int mf = 0; mf < MF; mf++) {
            uint32_t a[4];
            ldm_x4(a, sA + ((mBase + mf*16 + la)*KS + ks*16 + ka*8)*2);
#pragma unroll
            for (int nf = 0; nf < NF; nf++)
                mma_bf16(acc[mf][nf], a[0], a[1], a[2], a[3],
                         b[nf][0], b[nf][1]);
        }
    }
}

// ---------------------------------------------------------------------------
// Weight re-layout / conversion kernels
// ---------------------------------------------------------------------------
__global__ void reorder_w1_k(const float* __restrict__ w) {
    int idx = blockIdx.x * blockDim.x + threadIdx.x;
    int n = idx / K1, k = idx % K1;
    int t = k / CI1, i = k % CI1;
    g_W1re[idx] = __float2bfloat16(w[(n*CI1 + i)*9 + t]);
}
__global__ void reorder_w2_k(const float* __restrict__ w) {
    int idx = blockIdx.x * blockDim.x + threadIdx.x;
    int n = idx / K2, k = idx % K2;
    int t = k / CI2, i = k % CI2;
    g_W2re[idx] = __float2bfloat16(w[(n*CI2 + i)*9 + t]);
}
// one block per output row n: stage the row in smem, both sides coalesced
__global__ __launch_bounds__(256) void reorder_pre_k(const float* __restrict__ w) {
    __shared__ float buf[FUSED];
    int n = blockIdx.x;
    for (int k = threadIdx.x; k < FUSED; k += 256) buf[k] = w[n*FUSED + k];
    __syncthreads();
    for (int k = threadIdx.x; k < FUSED; k += 256) {
        int src;
        if (k < 6272) { int pos = k >> 7, ch = k & 127; src = ch*49 + pos; }
        else src = k;
        g_preW[n*FUSED + k] = __float2bfloat16(buf[src]);
    }
}
// one launch converting both W_ih (4*G3H*HH) and Wa (8*HH*HH) to bf16
#define N4_WIH (4*G3H*HH/4)
#define N4_WA  (8*HH*HH/4)
__global__ void cvt_w_k(const float* __restrict__ wih, const float* __restrict__ wa) {
    int i = blockIdx.x * blockDim.x + threadIdx.x;
    const float* src; bf* dst;
    if (i < N4_WIH) { src = wih + i*4; dst = g_Wih + i*4; }
    else {
        int j = i - N4_WIH;
        if (j >= N4_WA) return;
        src = wa + j*4; dst = g_Wa + j*4;
    }
    float4 v = *(const float4*)src;
    uint2 o; o.x = pack_bf2(v.x, v.y); o.y = pack_bf2(v.z, v.w);
    *(uint2*)dst = o;
}

// ---------------------------------------------------------------------------
// Embedding gather -> padded activation [B][9*9][96] bf16, 16B stores
// ---------------------------------------------------------------------------
__global__ void embed_k(const int* __restrict__ obj, const int* __restrict__ col,
                        const int* __restrict__ sta,
                        const float* __restrict__ eo, const float* __restrict__ ec,
                        const float* __restrict__ es) {
    long idx = (long)blockIdx.x * blockDim.x + threadIdx.x;   // MCONV*12
    int sub = (int)(idx % 12);
    long cell = idx / 12;
    int b = (int)(cell / 49), pos = (int)(cell % 49);
    int r = pos / 7, c = pos % 7;
    int tbl = sub >> 2, j = sub & 3;
    int e; const float* tab;
    if (tbl == 0)      { e = obj[cell]; tab = eo; }
    else if (tbl == 1) { e = col[cell]; tab = ec; }
    else               { e = sta[cell]; tab = es; }
    float4 v0 = *(const float4*)(tab + e*32 + j*8);
    float4 v1 = *(const float4*)(tab + e*32 + j*8 + 4);
    uint4 o;
    o.x = pack_bf2(v0.x, v0.y); o.y = pack_bf2(v0.z, v0.w);
    o.z = pack_bf2(v1.x, v1.y); o.w = pack_bf2(v1.z, v1.w);
    *(uint4*)(g_xpad + ((long)(b*81 + (r+1)*9 + (c+1)))*CI1 + tbl*32 + j*8) = o;
}

__global__ void tail_k(const int* __restrict__ dir, const int* __restrict__ task,
                       const float* __restrict__ ed, const float* __restrict__ et) {
    int idx = blockIdx.x * blockDim.x + threadIdx.x;
    int b = idx / 24, sub = idx % 24;
    float4 v; int dst;
    if (sub < 8) { v = *(const float4*)(ed + dir[b]*32 + sub*4);  dst = 6272 + sub*4; }
    else { int j = sub - 8; v = *(const float4*)(et + task[b]*64 + j*4); dst = 6304 + j*4; }
    uint2 o; o.x = pack_bf2(v.x, v.y); o.y = pack_bf2(v.z, v.w);
    *(uint2*)(g_fused + (long)b*FUSED + dst) = o;
}

// ---------------------------------------------------------------------------
// conv1: implicit GEMM  M=401408, N=64, K=864 -> relu -> y1pad interior
// CTA 128x64, 8 warps (4x2), warp tile 32x32; 3-stage cp.async, 1 sync/tile
// ---------------------------------------------------------------------------
__global__ __launch_bounds__(256) void conv1_k(const float* __restrict__ bias) {
    extern __shared__ __align__(16) bf smem1[];
    const int stageE = (128 + 64)*KS;          // bf16 elements per stage
    int m0 = blockIdx.x * 128;
    int tid = threadIdx.x;
    int warp = tid >> 5, lane = tid & 31;
    int lq = lane >> 2, lr = lane & 3;
    int mBase = (warp >> 1) * 32, nBase = (warp & 1) * 32;
    uint32_t sbase = (uint32_t)__cvta_generic_to_shared(smem1);

    float4 acc[2][4];
#pragma unroll
    for (int i = 0; i < 2; i++)
#pragma unroll
        for (int j = 0; j < 4; j++) acc[i][j] = make_float4(0.f,0.f,0.f,0.f);

    const int KT = K1/32;                       // 27
    auto load_tile = [&](int kt, int buf) {
        int k0 = kt*32;
        int tap = k0 / CI1;
        int i0  = k0 - tap*CI1;
        int offp = ((tap/3)*9 + (tap%3)) * CI1;
        uint32_t sb = sbase + buf*stageE*2;
#pragma unroll
        for (int it = 0; it < 3; it++) {
            int c = tid + it*256;               // 768 16B chunks
            const bf* src; uint32_t dst;
            if (c < 512) {
                int row = c >> 2, kc = c & 3;
                int m = m0 + row;
                int b = m/49, pos = m%49, r = pos/7, cc = pos%7;
                src = g_xpad + (long)(b*81 + r*9 + cc)*CI1 + offp + i0 + kc*8;
                dst = sb + (row*KS + kc*8)*2;
            } else {
                int row = (c - 512) >> 2, kc = c & 3;
                src = g_W1re + row*K1 + k0 + kc*8;
                dst = sb + (128*KS + row*KS + kc*8)*2;
            }
            cpa16(dst, src);
        }
        CP_COMMIT();
    };

    load_tile(0, 0); load_tile(1, 1);
    for (int kt = 0; kt < KT; kt++) {
        if (kt + 1 < KT) { CP_WAIT1(); } else { CP_WAIT0(); }
        __syncthreads();
        if (kt + 2 < KT) load_tile(kt + 2, (kt + 2) % 3);
        uint32_t sA = sbase + (kt % 3)*stageE*2;
        tile_mma_ldm<2,4>(sA, sA + 128*KS*2, mBase, nBase, lane, acc);
    }

#pragma unroll
    for (int mf = 0; mf < 2; mf++) {
#pragma unroll
        for (int half = 0; half < 2; half++) {
            int m = m0 + mBase + mf*16 + lq + half*8;
            int b = m/49, pos = m%49, r = pos/7, c = pos%7;
            bf* dst = g_y1pad + (long)(b*81 + (r+1)*9 + (c+1)) * CI2;
#pragma unroll
            for (int nf = 0; nf < 4; nf++) {
                int n = nBase + nf*8 + lr*2;
                float x0 = (half ? acc[mf][nf].z : acc[mf][nf].x) + bias[n];
                float x1 = (half ? acc[mf][nf].w : acc[mf][nf].y) + bias[n+1];
                *(uint32_t*)(dst + n) = pack_bf2(fmaxf(x0,0.f), fmaxf(x1,0.f));
            }
        }
    }
}

// ---------------------------------------------------------------------------
// conv2: implicit GEMM  M=401408, N=128, K=576 -> relu -> fused[pos*128+ch]
// CTA 128x128, 8 warps (2x4), warp tile 64x32; 3-stage, 1 sync/tile
// ---------------------------------------------------------------------------
__global__ __launch_bounds__(256) void conv2_k(const float* __restrict__ bias) {
    extern __shared__ __align__(16) bf smem2[];
    const int stageE = (128 + 128)*KS;
    int m0 = blockIdx.x * 128;
    int tid = threadIdx.x;
    int warp = tid >> 5, lane = tid & 31;
    int lq = lane >> 2, lr = lane & 3;
    int mBase = (warp >> 2) * 64, nBase = (warp & 3) * 32;
    uint32_t sbase = (uint32_t)__cvta_generic_to_shared(smem2);

    float4 acc[4][4];
#pragma unroll
    for (int i = 0; i < 4; i++)
#pragma unroll
        for (int j = 0; j < 4; j++) acc[i][j] = make_float4(0.f,0.f,0.f,0.f);

    const int KT = K2/32;                       // 18
    auto load_tile = [&](int kt, int buf) {
        int k0 = kt*32;
        int tap = k0 / CI2;
        int i0  = k0 - tap*CI2;
        int offp = ((tap/3)*9 + (tap%3)) * CI2;
        uint32_t sb = sbase + buf*stageE*2;
#pragma unroll
        for (int it = 0; it < 4; it++) {
            int c = tid + it*256;               // 1024 16B chunks
            const bf* src; uint32_t dst;
            if (c < 512) {
                int row = c >> 2, kc = c & 3;
                int m = m0 + row;
                int b = m/49, pos = m%49, r = pos/7, cc = pos%7;
                src = g_y1pad + (long)(b*81 + r*9 + cc)*CI2 + offp + i0 + kc*8;
                dst = sb + (row*KS + kc*8)*2;
            } else {
                int row = (c - 512) >> 2, kc = c & 3;
                src = g_W2re + row*K2 + k0 + kc*8;
                dst = sb + (128*KS + row*KS + kc*8)*2;
            }
            cpa16(dst, src);
        }
        CP_COMMIT();
    };

    load_tile(0, 0); load_tile(1, 1);
    for (int kt = 0; kt < KT; kt++) {
        if (kt + 1 < KT) { CP_WAIT1(); } else { CP_WAIT0(); }
        __syncthreads();
        if (kt + 2 < KT) load_tile(kt + 2, (kt + 2) % 3);
        uint32_t sA = sbase + (kt % 3)*stageE*2;
        tile_mma_ldm<4,4>(sA, sA + 128*KS*2, mBase, nBase, lane, acc);
    }

#pragma unroll
    for (int mf = 0; mf < 4; mf++) {
#pragma unroll
        for (int half = 0; half < 2; half++) {
            int m = m0 + mBase + mf*16 + lq + half*8;
            int b = m/49, pos = m%49;
            bf* dst = g_fused + (long)b*FUSED + pos*128;
#pragma unroll
            for (int nf = 0; nf < 4; nf++) {
                int n = nBase + nf*8 + lr*2;
                float x0 = (half ? acc[mf][nf].z : acc[mf][nf].x) + bias[n];
                float x1 = (half ? acc[mf][nf].w : acc[mf][nf].y) + bias[n+1];
                *(uint32_t*)(dst + n) = pack_bf2(fmaxf(x0,0.f), fmaxf(x1,0.f));
            }
        }
    }
}

// ---------------------------------------------------------------------------
// Generic TN GEMM (bf16 MMA, 3-stage cp.async, ldmatrix):
// C[m,n] = act( sum_k A[m,k]*W[n,k] + bias[n] ); optional perm gather,
// grouped M-tiles; output f32 (Cf) or bf16 (Cb).  CTA 128x128.
// ---------------------------------------------------------------------------
__global__ __launch_bounds__(256) void gemm_bf(
    const bf* __restrict__ A, int lda,
    const int* __restrict__ perm,
    const bf* __restrict__ Wg, long long wStride,
    const float* __restrict__ biasg, int biasStride,
    float* __restrict__ Cf, bf* __restrict__ Cb, int ldc,
    int K, int relu, int denseM,
    const int* __restrict__ tileG, const int* __restrict__ tileM0,
    const int* __restrict__ tileE, const int* __restrict__ nTilesPtr)
{
    extern __shared__ __align__(16) bf smemg[];
    const int stageE = (128 + 128)*KS;
    int m0, mEnd, g;
    if (tileG) {
        int t = blockIdx.x;
        if (t >= *nTilesPtr) return;
        g = tileG[t]; m0 = tileM0[t]; mEnd = tileE[t];
    } else {
        g = 0; m0 = blockIdx.x * 128; mEnd = denseM;
    }
    const bf* W = Wg + (long long)g * wStride;
    const float* bias = biasg + g * biasStride;
    int n0 = blockIdx.y * 128;

    int tid = threadIdx.x;
    int warp = tid >> 5, lane = tid & 31;
    int lq = lane >> 2, lr = lane & 3;
    int mBase = (warp >> 2) * 64, nBase = (warp & 3) * 32;
    uint32_t sbase = (uint32_t)__cvta_generic_to_shared(smemg);

    float4 acc[4][4];
#pragma unroll
    for (int i = 0; i < 4; i++)
#pragma unroll
        for (int j = 0; j < 4; j++) acc[i][j] = make_float4(0.f,0.f,0.f,0.f);

    const int KT = K/32;
    auto load_tile = [&](int kt, int buf) {
        int k0 = kt*32;
        uint32_t sb = sbase + buf*stageE*2;
#pragma unroll
        for (int it = 0; it < 4; it++) {
            int c = tid + it*256;
            const bf* src; uint32_t dst; int sz = 16;
            if (c < 512) {
                int row = c >> 2, kc = c & 3;
                int m = m0 + row;
                long ar = 0;
                if (m < mEnd) ar = perm ? perm[m] : m; else sz = 0;
                src = A + ar*lda + k0 + kc*8;
                dst = sb + (row*KS + kc*8)*2;
            } else {
                int row = (c - 512) >> 2, kc = c & 3;
                src = W + (long)(n0 + row)*K + k0 + kc*8;
                dst = sb + (128*KS + row*KS + kc*8)*2;
            }
            cpa16p(dst, src, sz);
        }
        CP_COMMIT();
    };

    load_tile(0, 0); load_tile(1, 1);
    for (int kt = 0; kt < KT; kt++) {
        if (kt + 1 < KT) { CP_WAIT1(); } else { CP_WAIT0(); }
        __syncthreads();
        if (kt + 2 < KT) load_tile(kt + 2, (kt + 2) % 3);
        uint32_t sA = sbase + (kt % 3)*stageE*2;
        tile_mma_ldm<4,4>(sA, sA + 128*KS*2, mBase, nBase, lane, acc);
    }

#pragma unroll
    for (int mf = 0; mf < 4; mf++) {
#pragma unroll
        for (int half = 0; half < 2; half++) {
            int m = m0 + mBase + mf*16 + lq + half*8;
            if (m >= mEnd) continue;
#pragma unroll
            for (int nf = 0; nf < 4; nf++) {
                int n = n0 + nBase + nf*8 + lr*2;
                float x0 = (half ? acc[mf][nf].z : acc[mf][nf].x) + bias[n];
                float x1 = (half ? acc[mf][nf].w : acc[mf][nf].y) + bias[n+1];
                if (relu) { x0 = fmaxf(x0, 0.f); x1 = fmaxf(x1, 0.f); }
                if (Cb) {
                    *(uint32_t*)(Cb + (long)m*ldc + n) = pack_bf2(x0, x1);
                } else {
                    float2 v; v.x = x0; v.y = x1;
                    *(float2*)(Cf + (long)m*ldc + n) = v;
                }
            }
        }
    }
}

// ---------------------------------------------------------------------------
// Task sort / compaction (g_counts self-zeroes: consumed by scatter)
// ---------------------------------------------------------------------------
__global__ void sort_count_k(const int* __restrict__ task) {
    int b = blockIdx.x * blockDim.x + threadIdx.x;
    if (b < BB) atomicAdd(&g_counts[task[b]], 1);
}
__global__ void sort_off_k() {
    if (threadIdx.x == 0 && blockIdx.x == 0) {
        int off = 0;
        for (int t = 0; t < 8; t++) { g_off[t] = off; off += g_counts[t]; }
        g_off[8] = off;
        int idx = 0;
        for (int g = 0; g < 4; g++) {
            int s = g_off[g];
            int e = (g < 3) ? g_off[g+1] : BB;
            for (int m0 = s; m0 < e; m0 += 128) {
                g_tileG[idx] = g; g_tileM0[idx] = m0; g_tileE[idx] = e; idx++;
            }
        }
        g_nGru[0] = idx;
        idx = 0;
        for (int t = 0; t < 8; t++) {
            int s = g_off[t], e = g_off[t+1];
            for (int m0 = s; m0 < e; m0 += 128) {
                g_tileT[idx] = t; g_tileM0a[idx] = m0; g_tileEa[idx] = e; idx++;
            }
        }
        g_nAd[0] = idx;
    }
}
__global__ void sort_scatter_k(const int* __restrict__ task) {
    int b = blockIdx.x * blockDim.x + threadIdx.x;
    if (b < BB) {
        int t = task[b];
        int r = atomicSub(&g_counts[t], 1) - 1;   // consumes counts -> zero
        int p = g_off[t] + r;
        g_perm[p] = b;
        g_rowTask[p] = t;
    }
}

// ---------------------------------------------------------------------------
// GRU elementwise (h0 = 0), float4-vectorized: 128 threads, 4 h per thread
// ---------------------------------------------------------------------------
__global__ void gru_elem_k(const float* __restrict__ b_hh) {
    int p = blockIdx.x, h4 = threadIdx.x;                 // h4 = 0..127
    int t = g_rowTask[p];
    int g = (t < 3) ? t : 3;
    const float4* gxr = (const float4*)(g_gx + (long)p*G3H);
    const float4* bh  = (const float4*)(b_hh + g*G3H);
    float4 rx = gxr[h4],       rb = bh[h4];
    float4 zx = gxr[128 + h4], zb = bh[128 + h4];
    float4 nx = gxr[256 + h4], nb = bh[256 + h4];
    float o[4];
#pragma unroll
    for (int i = 0; i < 4; i++) {
        float rxi = (&rx.x)[i], zxi = (&zx.x)[i], nxi = (&nx.x)[i];
        float rbi = (&rb.x)[i], zbi = (&zb.x)[i], nbi = (&nb.x)[i];
        float r = 1.f / (1.f + expf(-(rxi + rbi)));
        float z = 1.f / (1.f + expf(-(zxi + zbi)));
        float n = tanhf(nxi + r * nbi);
        o[i] = (1.f - z) * n;
    }
    uint2 ov;
    ov.x = pack_bf2(o[0], o[1]);
    ov.y = pack_bf2(o[2], o[3]);
    *(uint2*)(g_lat2 + (long)p*HH + h4*4) = ov;
}

// ---------------------------------------------------------------------------
// Heads: 7 logits + value per sample, float4-vectorized loads
// ---------------------------------------------------------------------------
__global__ void heads_k(const float* __restrict__ Wh, const float* __restrict__ bh2,
                        const float* __restrict__ vw, const float* __restrict__ vb,
                        float* __restrict__ out) {
    int p = blockIdx.x * 8 + (threadIdx.x >> 5);
    int lane = threadIdx.x & 31;
    if (p >= BB) return;
    int t = g_rowTask[p];
    int borig = g_perm[p];
    const float4* lrow = (const float4*)(g_lat3 + (long)p*HH);
    const float4* wt   = (const float4*)(Wh + t*7*HH);
    const float4* vw4  = (const float4*)vw;
    float acc[8];
#pragma unroll
    for (int a = 0; a < 8; a++) acc[a] = 0.f;
#pragma unroll
    for (int it = 0; it < 4; it++) {
        int h4 = lane + it*32;                            // float4 index, 0..127
        float4 x = lrow[h4];
#pragma unroll
        for (int a = 0; a < 7; a++) {
            float4 w = wt[a*128 + h4];
            acc[a] += x.x*w.x + x.y*w.y + x.z*w.z + x.w*w.w;
        }
        float4 v = vw4[h4];
        acc[7] += x.x*v.x + x.y*v.y + x.z*v.z + x.w*v.w;
    }
#pragma unroll
    for (int a = 0; a < 8; a++)
#pragma unroll
        for (int off = 16; off; off >>= 1)
            acc[a] += __shfl_down_sync(0xffffffff, acc[a], off);
    if (lane == 0) {
#pragma unroll
        for (int a = 0; a < 7; a++) out[borig*7 + a] = acc[a] + bh2[t*7 + a];
        out[BB*7 + borig] = acc[7] + vb[0];
    }
}

// ---------------------------------------------------------------------------
// Launch
// ---------------------------------------------------------------------------
extern "C" void kernel_launch(void* const* d_in, const int* in_sizes, int n_in,
                              void* d_out, int out_size) {
    const int*   obj   = (const int*)  d_in[0];
    const int*   color = (const int*)  d_in[1];
    const int*   state = (const int*)  d_in[2];
    const int*   dir   = (const int*)  d_in[3];
    const int*   task  = (const int*)  d_in[4];
    const float* eo    = (const float*)d_in[5];
    const float* ec    = (const float*)d_in[6];
    const float* es    = (const float*)d_in[7];
    const float* ed    = (const float*)d_in[8];
    const float* et    = (const float*)d_in[9];
    const float* c1w   = (const float*)d_in[10];
    const float* c1b   = (const float*)d_in[11];
    const float* c2w   = (const float*)d_in[12];
    const float* c2b   = (const float*)d_in[13];
    const float* prew  = (const float*)d_in[14];
    const float* preb  = (const float*)d_in[15];
    const float* W_ih  = (const float*)d_in[16];
    const float* b_ih  = (const float*)d_in[18];
    const float* b_hh  = (const float*)d_in[19];
    const float* Wa    = (const float*)d_in[20];
    const float* ba    = (const float*)d_in[21];
    const float* Wh    = (const float*)d_in[22];
    const float* bh2   = (const float*)d_in[23];
    const float* vw    = (const float*)d_in[24];
    const float* vb    = (const float*)d_in[25];
    float* out = (float*)d_out;

    bf *p_fused, *p_preW, *p_lat, *p_lat2, *p_Wih, *p_Wa;
    float *p_gx, *p_lat3;
    int *p_perm, *p_tG, *p_tM0, *p_tE, *p_nG, *p_tT, *p_tM0a, *p_tEa, *p_nA;
    cudaGetSymbolAddress((void**)&p_fused, g_fused);
    cudaGetSymbolAddress((void**)&p_preW,  g_preW);
    cudaGetSymbolAddress((void**)&p_lat,   g_lat);
    cudaGetSymbolAddress((void**)&p_gx,    g_gx);
    cudaGetSymbolAddress((void**)&p_lat2,  g_lat2);
    cudaGetSymbolAddress((void**)&p_lat3,  g_lat3);
    cudaGetSymbolAddress((void**)&p_Wih,   g_Wih);
    cudaGetSymbolAddress((void**)&p_Wa,    g_Wa);
    cudaGetSymbolAddress((void**)&p_perm,  g_perm);
    cudaGetSymbolAddress((void**)&p_tG,    g_tileG);
    cudaGetSymbolAddress((void**)&p_tM0,   g_tileM0);
    cudaGetSymbolAddress((void**)&p_tE,    g_tileE);
    cudaGetSymbolAddress((void**)&p_nG,    g_nGru);
    cudaGetSymbolAddress((void**)&p_tT,    g_tileT);
    cudaGetSymbolAddress((void**)&p_tM0a,  g_tileM0a);
    cudaGetSymbolAddress((void**)&p_tEa,   g_tileEa);
    cudaGetSymbolAddress((void**)&p_nA,    g_nAd);

    // weight re-layouts / conversions (f32 -> bf16)
    reorder_w1_k <<<216, 256>>>(c1w);
    reorder_w2_k <<<288, 256>>>(c2w);
    reorder_pre_k<<<512, 256>>>(prew);
    cvt_w_k<<<(N4_WIH + N4_WA + 255)/256, 256>>>(W_ih, Wa);

    // embedding gathers (16B stores)
    embed_k<<<18816, 256>>>(obj, color, state, eo, ec, es);
    tail_k <<<768,   256>>>(dir, task, ed, et);

    // dynamic smem: 3 stages
    const int smem1 = 3 * (128 + 64)  * KS * 2;   // 46080
    const int smem2 = 3 * (128 + 128) * KS * 2;   // 61440
    cudaFuncSetAttribute(conv1_k, cudaFuncAttributeMaxDynamicSharedMemorySize, smem1);
    cudaFuncSetAttribute(conv2_k, cudaFuncAttributeMaxDynamicSharedMemorySize, smem2);
    cudaFuncSetAttribute(gemm_bf, cudaFuncAttributeMaxDynamicSharedMemorySize, smem2);

    // convs (implicit GEMM, bf16 mma + ldmatrix + 3-stage cp.async)
    conv1_k<<<3136, 256, smem1>>>(c1b);
    conv2_k<<<3136, 256, smem2>>>(c2b);

    // pre-linear: M=8192, N=512, K=6368, relu, bf16 out
    gemm_bf<<<dim3(64, 4), 256, smem2>>>(p_fused, FUSED, nullptr,
                                  p_preW, 0, preb, 0,
                                  nullptr, p_lat, HH, FUSED, 1, BB,
                                  nullptr, nullptr, nullptr, nullptr);

    // task sort (counts self-zero via scatter's atomicSub)
    sort_count_k  <<<32, 256>>>(task);
    sort_off_k    <<<1,  1>>>();
    sort_scatter_k<<<32, 256>>>(task);

    // GRU gates: grouped (4 GRUs), perm gather; N=1536, K=512, f32 out
    gemm_bf<<<dim3(80, 12), 256, smem2>>>(p_lat, HH, p_perm,
                                   p_Wih, (long long)G3H*HH, b_ih, G3H,
                                   p_gx, nullptr, G3H, HH, 0, 0,
                                   p_tG, p_tM0, p_tE, p_nG);
    gru_elem_k<<<BB, 128>>>(b_hh);

    // adapter: grouped (8 tasks); N=512, K=512, relu, f32 out
    gemm_bf<<<dim3(80, 4), 256, smem2>>>(p_lat2, HH, nullptr,
                                  p_Wa, (long long)HH*HH, ba, HH,
                                  p_lat3, nullptr, HH, HH, 1, 0,
                                  p_tT, p_tM0a, p_tEa, p_nA);

    // policy heads + value
    heads_k<<<1024, 256>>>(Wh, bh2, vw, vb, out);
}

// round 17
// speedup vs baseline: 1.0965x; 1.0266x over previous
#include <cuda_runtime.h>
#include <cuda_bf16.h>
#include <math.h>
#include <stdint.h>

// ---------------------------------------------------------------------------
// Problem constants
// ---------------------------------------------------------------------------
#define BB     8192
#define NPOS   49
#define MCONV  (BB*NPOS)        // 401408
#define CI1    96
#define CO1    64
#define K1     (9*CI1)          // 864
#define CI2    64
#define CO2    128
#define K2     (9*CI2)          // 576
#define FUSED  6368
#define HH     512
#define G3H    1536
#define KS     40               // smem k-stride in bf16 (80B rows -> conflict-free)

typedef __nv_bfloat16 bf;

// ---------------------------------------------------------------------------
// Scratch (__device__ globals; zero-init at module load -> free SAME padding)
// ---------------------------------------------------------------------------
__device__ __align__(16) bf    g_xpad [BB*81*CI1];
__device__ __align__(16) bf    g_y1pad[BB*81*CI2];
__device__ __align__(16) bf    g_fused[BB*FUSED];
__device__ __align__(16) bf    g_W1re [CO1*K1];
__device__ __align__(16) bf    g_W2re [CO2*K2];
__device__ __align__(16) bf    g_preW [HH*FUSED];
__device__ __align__(16) bf    g_Wih  [4*G3H*HH];
__device__ __align__(16) bf    g_Wa   [8*HH*HH];
__device__ __align__(16) bf    g_lat  [BB*HH];
__device__ __align__(16) float g_gx   [BB*G3H];
__device__ __align__(16) bf    g_lat2 [BB*HH];
__device__ __align__(16) float g_lat3 [BB*HH];
__device__ int g_perm[BB], g_rowTask[BB];
__device__ int g_counts[8], g_off[9];
__device__ int g_tileG [80], g_tileM0 [80], g_tileE [80], g_nGru[1];
__device__ int g_tileT [80], g_tileM0a[80], g_tileEa[80], g_nAd[1];

// ---------------------------------------------------------------------------
// Helpers
// ---------------------------------------------------------------------------
__device__ __forceinline__ uint32_t pack_bf2(float lo, float hi) {
    __nv_bfloat162 p = __floats2bfloat162_rn(lo, hi);
    return *reinterpret_cast<uint32_t*>(&p);
}
__device__ __forceinline__ void cpa16(uint32_t dst, const void* src) {
    asm volatile("cp.async.cg.shared.global [%0], [%1], 16;\n"
                 :: "r"(dst), "l"(src));
}
__device__ __forceinline__ void cpa16p(uint32_t dst, const void* src, int sz) {
    asm volatile("cp.async.cg.shared.global [%0], [%1], 16, %2;\n"
                 :: "r"(dst), "l"(src), "r"(sz));
}
#define CP_COMMIT() asm volatile("cp.async.commit_group;\n" ::: "memory")
#define CP_WAIT0()  asm volatile("cp.async.wait_group 0;\n" ::: "memory")
#define CP_WAIT1()  asm volatile("cp.async.wait_group 1;\n" ::: "memory")

__device__ __forceinline__ void mma_bf16(float4& d,
    uint32_t a0, uint32_t a1, uint32_t a2, uint32_t a3,
    uint32_t b0, uint32_t b1)
{
    asm volatile(
        "mma.sync.aligned.m16n8k16.row.col.f32.bf16.bf16.f32 "
        "{%0,%1,%2,%3}, {%4,%5,%6,%7}, {%8,%9}, {%0,%1,%2,%3};\n"
        : "+f"(d.x), "+f"(d.y), "+f"(d.z), "+f"(d.w)
        : "r"(a0), "r"(a1), "r"(a2), "r"(a3), "r"(b0), "r"(b1));
}
__device__ __forceinline__ void ldm_x4(uint32_t (&r)[4], uint32_t addr) {
    asm volatile("ldmatrix.sync.aligned.m8n8.x4.shared.b16 {%0,%1,%2,%3}, [%4];"
                 : "=r"(r[0]), "=r"(r[1]), "=r"(r[2]), "=r"(r[3]) : "r"(addr));
}

// One k32 tile of MMAs over MF*16 x NF*8 warp tile, ldmatrix fragment loads.
template<int MF, int NF>
__device__ __forceinline__ void tile_mma_ldm(
    uint32_t sA, uint32_t sB, int mBase, int nBase, int lane,
    float4 (&acc)[MF][NF])
{
    int la = lane & 15, ka = lane >> 4;                 // A: row-in-16, k-half
    int nb = (lane & 7) + ((lane >> 4) << 3);           // B: n-row
    int kb = (lane >> 3) & 1;                           // B: k-half
#pragma unroll
    for (int ks = 0; ks < 2; ks++) {
        uint32_t b[NF][2];
#pragma unroll
        for (int p = 0; p < NF/2; p++) {
            uint32_t r[4];
            ldm_x4(r, sB + ((nBase + p*16 + nb)*KS + ks*16 + kb*8)*2);
            b[2*p  ][0] = r[0]; b[2*p  ][1] = r[1];
            b[2*p+1][0] = r[2]; b[2*p+1][1] = r[3];
        }
#pragma unroll
        for (int mf = 0; mf < MF; mf++) {
            uint32_t a[4];
            ldm_x4(a, sA + ((mBase + mf*16 + la)*KS + ks*16 + ka*8)*2);
#pragma unroll
            for (int nf = 0; nf < NF; nf++)
                mma_bf16(acc[mf][nf], a[0], a[1], a[2], a[3],
                         b[nf][0], b[nf][1]);
        }
    }
}

// ---------------------------------------------------------------------------
// Weight re-layout / conversion kernels
// ---------------------------------------------------------------------------
__global__ void reorder_w1_k(const float* __restrict__ w) {
    int idx = blockIdx.x * blockDim.x + threadIdx.x;
    int n = idx / K1, k = idx % K1;
    int t = k / CI1, i = k % CI1;
    g_W1re[idx] = __float2bfloat16(w[(n*CI1 + i)*9 + t]);
}
__global__ void reorder_w2_k(const float* __restrict__ w) {
    int idx = blockIdx.x * blockDim.x + threadIdx.x;
    int n = idx / K2, k = idx % K2;
    int t = k / CI2, i = k % CI2;
    g_W2re[idx] = __float2bfloat16(w[(n*CI2 + i)*9 + t]);
}
// one block per output row n: stage the row in smem, both sides coalesced
__global__ __launch_bounds__(256) void reorder_pre_k(const float* __restrict__ w) {
    __shared__ float buf[FUSED];
    int n = blockIdx.x;
    for (int k = threadIdx.x; k < FUSED; k += 256) buf[k] = w[n*FUSED + k];
    __syncthreads();
    for (int k = threadIdx.x; k < FUSED; k += 256) {
        int src;
        if (k < 6272) { int pos = k >> 7, ch = k & 127; src = ch*49 + pos; }
        else src = k;
        g_preW[n*FUSED + k] = __float2bfloat16(buf[src]);
    }
}
// one launch converting both W_ih (4*G3H*HH) and Wa (8*HH*HH) to bf16
#define N4_WIH (4*G3H*HH/4)
#define N4_WA  (8*HH*HH/4)
__global__ void cvt_w_k(const float* __restrict__ wih, const float* __restrict__ wa) {
    int i = blockIdx.x * blockDim.x + threadIdx.x;
    const float* src; bf* dst;
    if (i < N4_WIH) { src = wih + i*4; dst = g_Wih + i*4; }
    else {
        int j = i - N4_WIH;
        if (j >= N4_WA) return;
        src = wa + j*4; dst = g_Wa + j*4;
    }
    float4 v = *(const float4*)src;
    uint2 o; o.x = pack_bf2(v.x, v.y); o.y = pack_bf2(v.z, v.w);
    *(uint2*)dst = o;
}

// ---------------------------------------------------------------------------
// Embedding gather -> padded activation [B][9*9][96] bf16, 16B stores
// ---------------------------------------------------------------------------
__global__ void embed_k(const int* __restrict__ obj, const int* __restrict__ col,
                        const int* __restrict__ sta,
                        const float* __restrict__ eo, const float* __restrict__ ec,
                        const float* __restrict__ es) {
    long idx = (long)blockIdx.x * blockDim.x + threadIdx.x;   // MCONV*12
    int sub = (int)(idx % 12);
    long cell = idx / 12;
    int b = (int)(cell / 49), pos = (int)(cell % 49);
    int r = pos / 7, c = pos % 7;
    int tbl = sub >> 2, j = sub & 3;
    int e; const float* tab;
    if (tbl == 0)      { e = obj[cell]; tab = eo; }
    else if (tbl == 1) { e = col[cell]; tab = ec; }
    else               { e = sta[cell]; tab = es; }
    float4 v0 = *(const float4*)(tab + e*32 + j*8);
    float4 v1 = *(const float4*)(tab + e*32 + j*8 + 4);
    uint4 o;
    o.x = pack_bf2(v0.x, v0.y); o.y = pack_bf2(v0.z, v0.w);
    o.z = pack_bf2(v1.x, v1.y); o.w = pack_bf2(v1.z, v1.w);
    *(uint4*)(g_xpad + ((long)(b*81 + (r+1)*9 + (c+1)))*CI1 + tbl*32 + j*8) = o;
}

__global__ void tail_k(const int* __restrict__ dir, const int* __restrict__ task,
                       const float* __restrict__ ed, const float* __restrict__ et) {
    int idx = blockIdx.x * blockDim.x + threadIdx.x;
    int b = idx / 24, sub = idx % 24;
    float4 v; int dst;
    if (sub < 8) { v = *(const float4*)(ed + dir[b]*32 + sub*4);  dst = 6272 + sub*4; }
    else { int j = sub - 8; v = *(const float4*)(et + task[b]*64 + j*4); dst = 6304 + j*4; }
    uint2 o; o.x = pack_bf2(v.x, v.y); o.y = pack_bf2(v.z, v.w);
    *(uint2*)(g_fused + (long)b*FUSED + dst) = o;
}

// ---------------------------------------------------------------------------
// conv1: implicit GEMM  M=401408, N=64, K=864 -> relu -> y1pad interior
// CTA 128x64, 8 warps (4x2), warp tile 32x32; 3-stage cp.async, 1 sync/tile
// ---------------------------------------------------------------------------
__global__ __launch_bounds__(256) void conv1_k(const float* __restrict__ bias) {
    extern __shared__ __align__(16) bf smem1[];
    const int stageE = (128 + 64)*KS;          // bf16 elements per stage
    int m0 = blockIdx.x * 128;
    int tid = threadIdx.x;
    int warp = tid >> 5, lane = tid & 31;
    int lq = lane >> 2, lr = lane & 3;
    int mBase = (warp >> 1) * 32, nBase = (warp & 1) * 32;
    uint32_t sbase = (uint32_t)__cvta_generic_to_shared(smem1);

    float4 acc[2][4];
#pragma unroll
    for (int i = 0; i < 2; i++)
#pragma unroll
        for (int j = 0; j < 4; j++) acc[i][j] = make_float4(0.f,0.f,0.f,0.f);

    const int KT = K1/32;                       // 27
    auto load_tile = [&](int kt, int buf) {
        int k0 = kt*32;
        int tap = k0 / CI1;
        int i0  = k0 - tap*CI1;
        int offp = ((tap/3)*9 + (tap%3)) * CI1;
        uint32_t sb = sbase + buf*stageE*2;
#pragma unroll
        for (int it = 0; it < 3; it++) {
            int c = tid + it*256;               // 768 16B chunks
            const bf* src; uint32_t dst;
            if (c < 512) {
                int row = c >> 2, kc = c & 3;
                int m = m0 + row;
                int b = m/49, pos = m%49, r = pos/7, cc = pos%7;
                src = g_xpad + (long)(b*81 + r*9 + cc)*CI1 + offp + i0 + kc*8;
                dst = sb + (row*KS + kc*8)*2;
            } else {
                int row = (c - 512) >> 2, kc = c & 3;
                src = g_W1re + row*K1 + k0 + kc*8;
                dst = sb + (128*KS + row*KS + kc*8)*2;
            }
            cpa16(dst, src);
        }
        CP_COMMIT();
    };

    load_tile(0, 0); load_tile(1, 1);
    for (int kt = 0; kt < KT; kt++) {
        if (kt + 1 < KT) { CP_WAIT1(); } else { CP_WAIT0(); }
        __syncthreads();
        if (kt + 2 < KT) load_tile(kt + 2, (kt + 2) % 3);
        uint32_t sA = sbase + (kt % 3)*stageE*2;
        tile_mma_ldm<2,4>(sA, sA + 128*KS*2, mBase, nBase, lane, acc);
    }

#pragma unroll
    for (int mf = 0; mf < 2; mf++) {
#pragma unroll
        for (int half = 0; half < 2; half++) {
            int m = m0 + mBase + mf*16 + lq + half*8;
            int b = m/49, pos = m%49, r = pos/7, c = pos%7;
            bf* dst = g_y1pad + (long)(b*81 + (r+1)*9 + (c+1)) * CI2;
#pragma unroll
            for (int nf = 0; nf < 4; nf++) {
                int n = nBase + nf*8 + lr*2;
                float x0 = (half ? acc[mf][nf].z : acc[mf][nf].x) + bias[n];
                float x1 = (half ? acc[mf][nf].w : acc[mf][nf].y) + bias[n+1];
                *(uint32_t*)(dst + n) = pack_bf2(fmaxf(x0,0.f), fmaxf(x1,0.f));
            }
        }
    }
}

// ---------------------------------------------------------------------------
// conv2: implicit GEMM  M=401408, N=128, K=576 -> relu -> fused[pos*128+ch]
// CTA 128x128, 8 warps (2x4), warp tile 64x32; 3-stage, 1 sync/tile
// ---------------------------------------------------------------------------
__global__ __launch_bounds__(256) void conv2_k(const float* __restrict__ bias) {
    extern __shared__ __align__(16) bf smem2[];
    const int stageE = (128 + 128)*KS;
    int m0 = blockIdx.x * 128;
    int tid = threadIdx.x;
    int warp = tid >> 5, lane = tid & 31;
    int lq = lane >> 2, lr = lane & 3;
    int mBase = (warp >> 2) * 64, nBase = (warp & 3) * 32;
    uint32_t sbase = (uint32_t)__cvta_generic_to_shared(smem2);

    float4 acc[4][4];
#pragma unroll
    for (int i = 0; i < 4; i++)
#pragma unroll
        for (int j = 0; j < 4; j++) acc[i][j] = make_float4(0.f,0.f,0.f,0.f);

    const int KT = K2/32;                       // 18
    auto load_tile = [&](int kt, int buf) {
        int k0 = kt*32;
        int tap = k0 / CI2;
        int i0  = k0 - tap*CI2;
        int offp = ((tap/3)*9 + (tap%3)) * CI2;
        uint32_t sb = sbase + buf*stageE*2;
#pragma unroll
        for (int it = 0; it < 4; it++) {
            int c = tid + it*256;               // 1024 16B chunks
            const bf* src; uint32_t dst;
            if (c < 512) {
                int row = c >> 2, kc = c & 3;
                int m = m0 + row;
                int b = m/49, pos = m%49, r = pos/7, cc = pos%7;
                src = g_y1pad + (long)(b*81 + r*9 + cc)*CI2 + offp + i0 + kc*8;
                dst = sb + (row*KS + kc*8)*2;
            } else {
                int row = (c - 512) >> 2, kc = c & 3;
                src = g_W2re + row*K2 + k0 + kc*8;
                dst = sb + (128*KS + row*KS + kc*8)*2;
            }
            cpa16(dst, src);
        }
        CP_COMMIT();
    };

    load_tile(0, 0); load_tile(1, 1);
    for (int kt = 0; kt < KT; kt++) {
        if (kt + 1 < KT) { CP_WAIT1(); } else { CP_WAIT0(); }
        __syncthreads();
        if (kt + 2 < KT) load_tile(kt + 2, (kt + 2) % 3);
        uint32_t sA = sbase + (kt % 3)*stageE*2;
        tile_mma_ldm<4,4>(sA, sA + 128*KS*2, mBase, nBase, lane, acc);
    }

#pragma unroll
    for (int mf = 0; mf < 4; mf++) {
#pragma unroll
        for (int half = 0; half < 2; half++) {
            int m = m0 + mBase + mf*16 + lq + half*8;
            int b = m/49, pos = m%49;
            bf* dst = g_fused + (long)b*FUSED + pos*128;
#pragma unroll
            for (int nf = 0; nf < 4; nf++) {
                int n = nBase + nf*8 + lr*2;
                float x0 = (half ? acc[mf][nf].z : acc[mf][nf].x) + bias[n];
                float x1 = (half ? acc[mf][nf].w : acc[mf][nf].y) + bias[n+1];
                *(uint32_t*)(dst + n) = pack_bf2(fmaxf(x0,0.f), fmaxf(x1,0.f));
            }
        }
    }
}

// ---------------------------------------------------------------------------
// Generic TN GEMM (bf16 MMA, 3-stage cp.async, ldmatrix):
// C[m,n] = act( sum_k A[m,k]*W[n,k] + bias[n] ); optional perm gather,
// grouped M-tiles; output f32 (Cf) or bf16 (Cb).  CTA 128x128.
// ---------------------------------------------------------------------------
__global__ __launch_bounds__(256) void gemm_bf(
    const bf* __restrict__ A, int lda,
    const int* __restrict__ perm,
    const bf* __restrict__ Wg, long long wStride,
    const float* __restrict__ biasg, int biasStride,
    float* __restrict__ Cf, bf* __restrict__ Cb, int ldc,
    int K, int relu, int denseM,
    const int* __restrict__ tileG, const int* __restrict__ tileM0,
    const int* __restrict__ tileE, const int* __restrict__ nTilesPtr)
{
    extern __shared__ __align__(16) bf smemg[];
    const int stageE = (128 + 128)*KS;
    int m0, mEnd, g;
    if (tileG) {
        int t = blockIdx.x;
        if (t >= *nTilesPtr) return;
        g = tileG[t]; m0 = tileM0[t]; mEnd = tileE[t];
    } else {
        g = 0; m0 = blockIdx.x * 128; mEnd = denseM;
    }
    const bf* W = Wg + (long long)g * wStride;
    const float* bias = biasg + g * biasStride;
    int n0 = blockIdx.y * 128;

    int tid = threadIdx.x;
    int warp = tid >> 5, lane = tid & 31;
    int lq = lane >> 2, lr = lane & 3;
    int mBase = (warp >> 2) * 64, nBase = (warp & 3) * 32;
    uint32_t sbase = (uint32_t)__cvta_generic_to_shared(smemg);

    float4 acc[4][4];
#pragma unroll
    for (int i = 0; i < 4; i++)
#pragma unroll
        for (int j = 0; j < 4; j++) acc[i][j] = make_float4(0.f,0.f,0.f,0.f);

    const int KT = K/32;
    auto load_tile = [&](int kt, int buf) {
        int k0 = kt*32;
        uint32_t sb = sbase + buf*stageE*2;
#pragma unroll
        for (int it = 0; it < 4; it++) {
            int c = tid + it*256;
            const bf* src; uint32_t dst; int sz = 16;
            if (c < 512) {
                int row = c >> 2, kc = c & 3;
                int m = m0 + row;
                long ar = 0;
                if (m < mEnd) ar = perm ? perm[m] : m; else sz = 0;
                src = A + ar*lda + k0 + kc*8;
                dst = sb + (row*KS + kc*8)*2;
            } else {
                int row = (c - 512) >> 2, kc = c & 3;
                src = W + (long)(n0 + row)*K + k0 + kc*8;
                dst = sb + (128*KS + row*KS + kc*8)*2;
            }
            cpa16p(dst, src, sz);
        }
        CP_COMMIT();
    };

    load_tile(0, 0); load_tile(1, 1);
    for (int kt = 0; kt < KT; kt++) {
        if (kt + 1 < KT) { CP_WAIT1(); } else { CP_WAIT0(); }
        __syncthreads();
        if (kt + 2 < KT) load_tile(kt + 2, (kt + 2) % 3);
        uint32_t sA = sbase + (kt % 3)*stageE*2;
        tile_mma_ldm<4,4>(sA, sA + 128*KS*2, mBase, nBase, lane, acc);
    }

#pragma unroll
    for (int mf = 0; mf < 4; mf++) {
#pragma unroll
        for (int half = 0; half < 2; half++) {
            int m = m0 + mBase + mf*16 + lq + half*8;
            if (m >= mEnd) continue;
#pragma unroll
            for (int nf = 0; nf < 4; nf++) {
                int n = n0 + nBase + nf*8 + lr*2;
                float x0 = (half ? acc[mf][nf].z : acc[mf][nf].x) + bias[n];
                float x1 = (half ? acc[mf][nf].w : acc[mf][nf].y) + bias[n+1];
                if (relu) { x0 = fmaxf(x0, 0.f); x1 = fmaxf(x1, 0.f); }
                if (Cb) {
                    *(uint32_t*)(Cb + (long)m*ldc + n) = pack_bf2(x0, x1);
                } else {
                    float2 v; v.x = x0; v.y = x1;
                    *(float2*)(Cf + (long)m*ldc + n) = v;
                }
            }
        }
    }
}

// ---------------------------------------------------------------------------
// Task sort / compaction (g_counts self-zeroes: consumed by scatter)
// ---------------------------------------------------------------------------
__global__ void sort_count_k(const int* __restrict__ task) {
    int b = blockIdx.x * blockDim.x + threadIdx.x;
    if (b < BB) atomicAdd(&g_counts[task[b]], 1);
}
__global__ void sort_off_k() {
    if (threadIdx.x == 0 && blockIdx.x == 0) {
        int off = 0;
        for (int t = 0; t < 8; t++) { g_off[t] = off; off += g_counts[t]; }
        g_off[8] = off;
        int idx = 0;
        for (int g = 0; g < 4; g++) {
            int s = g_off[g];
            int e = (g < 3) ? g_off[g+1] : BB;
            for (int m0 = s; m0 < e; m0 += 128) {
                g_tileG[idx] = g; g_tileM0[idx] = m0; g_tileE[idx] = e; idx++;
            }
        }
        g_nGru[0] = idx;
        idx = 0;
        for (int t = 0; t < 8; t++) {
            int s = g_off[t], e = g_off[t+1];
            for (int m0 = s; m0 < e; m0 += 128) {
                g_tileT[idx] = t; g_tileM0a[idx] = m0; g_tileEa[idx] = e; idx++;
            }
        }
        g_nAd[0] = idx;
    }
}
__global__ void sort_scatter_k(const int* __restrict__ task) {
    int b = blockIdx.x * blockDim.x + threadIdx.x;
    if (b < BB) {
        int t = task[b];
        int r = atomicSub(&g_counts[t], 1) - 1;   // consumes counts -> zero
        int p = g_off[t] + r;
        g_perm[p] = b;
        g_rowTask[p] = t;
    }
}

// ---------------------------------------------------------------------------
// GRU elementwise (h0 = 0), float4-vectorized: 128 threads, 4 h per thread
// ---------------------------------------------------------------------------
__global__ void gru_elem_k(const float* __restrict__ b_hh) {
    int p = blockIdx.x, h4 = threadIdx.x;                 // h4 = 0..127
    int t = g_rowTask[p];
    int g = (t < 3) ? t : 3;
    const float4* gxr = (const float4*)(g_gx + (long)p*G3H);
    const float4* bh  = (const float4*)(b_hh + g*G3H);
    float4 rx = gxr[h4],       rb = bh[h4];
    float4 zx = gxr[128 + h4], zb = bh[128 + h4];
    float4 nx = gxr[256 + h4], nb = bh[256 + h4];
    float o[4];
#pragma unroll
    for (int i = 0; i < 4; i++) {
        float rxi = (&rx.x)[i], zxi = (&zx.x)[i], nxi = (&nx.x)[i];
        float rbi = (&rb.x)[i], zbi = (&zb.x)[i], nbi = (&nb.x)[i];
        float r = 1.f / (1.f + expf(-(rxi + rbi)));
        float z = 1.f / (1.f + expf(-(zxi + zbi)));
        float n = tanhf(nxi + r * nbi);
        o[i] = (1.f - z) * n;
    }
    uint2 ov;
    ov.x = pack_bf2(o[0], o[1]);
    ov.y = pack_bf2(o[2], o[3]);
    *(uint2*)(g_lat2 + (long)p*HH + h4*4) = ov;
}

// ---------------------------------------------------------------------------
// Heads: 7 logits + value per sample, float4-vectorized loads
// ---------------------------------------------------------------------------
__global__ void heads_k(const float* __restrict__ Wh, const float* __restrict__ bh2,
                        const float* __restrict__ vw, const float* __restrict__ vb,
                        float* __restrict__ out) {
    int p = blockIdx.x * 8 + (threadIdx.x >> 5);
    int lane = threadIdx.x & 31;
    if (p >= BB) return;
    int t = g_rowTask[p];
    int borig = g_perm[p];
    const float4* lrow = (const float4*)(g_lat3 + (long)p*HH);
    const float4* wt   = (const float4*)(Wh + t*7*HH);
    const float4* vw4  = (const float4*)vw;
    float acc[8];
#pragma unroll
    for (int a = 0; a < 8; a++) acc[a] = 0.f;
#pragma unroll
    for (int it = 0; it < 4; it++) {
        int h4 = lane + it*32;                            // float4 index, 0..127
        float4 x = lrow[h4];
#pragma unroll
        for (int a = 0; a < 7; a++) {
            float4 w = wt[a*128 + h4];
            acc[a] += x.x*w.x + x.y*w.y + x.z*w.z + x.w*w.w;
        }
        float4 v = vw4[h4];
        acc[7] += x.x*v.x + x.y*v.y + x.z*v.z + x.w*v.w;
    }
#pragma unroll
    for (int a = 0; a < 8; a++)
#pragma unroll
        for (int off = 16; off; off >>= 1)
            acc[a] += __shfl_down_sync(0xffffffff, acc[a], off);
    if (lane == 0) {
#pragma unroll
        for (int a = 0; a < 7; a++) out[borig*7 + a] = acc[a] + bh2[t*7 + a];
        out[BB*7 + borig] = acc[7] + vb[0];
    }
}

// ---------------------------------------------------------------------------
// Launch: fork/join two-stream schedule (capture-legal event pattern).
// Side stream: weight re-layouts + tail + sort (independent of conv chain).
// Main stream: embed -> (wait W1/W2) convs -> (wait rest) pre -> ... -> heads
// ---------------------------------------------------------------------------
extern "C" void kernel_launch(void* const* d_in, const int* in_sizes, int n_in,
                              void* d_out, int out_size) {
    const int*   obj   = (const int*)  d_in[0];
    const int*   color = (const int*)  d_in[1];
    const int*   state = (const int*)  d_in[2];
    const int*   dir   = (const int*)  d_in[3];
    const int*   task  = (const int*)  d_in[4];
    const float* eo    = (const float*)d_in[5];
    const float* ec    = (const float*)d_in[6];
    const float* es    = (const float*)d_in[7];
    const float* ed    = (const float*)d_in[8];
    const float* et    = (const float*)d_in[9];
    const float* c1w   = (const float*)d_in[10];
    const float* c1b   = (const float*)d_in[11];
    const float* c2w   = (const float*)d_in[12];
    const float* c2b   = (const float*)d_in[13];
    const float* prew  = (const float*)d_in[14];
    const float* preb  = (const float*)d_in[15];
    const float* W_ih  = (const float*)d_in[16];
    const float* b_ih  = (const float*)d_in[18];
    const float* b_hh  = (const float*)d_in[19];
    const float* Wa    = (const float*)d_in[20];
    const float* ba    = (const float*)d_in[21];
    const float* Wh    = (const float*)d_in[22];
    const float* bh2   = (const float*)d_in[23];
    const float* vw    = (const float*)d_in[24];
    const float* vb    = (const float*)d_in[25];
    float* out = (float*)d_out;

    bf *p_fused, *p_preW, *p_lat, *p_lat2, *p_Wih, *p_Wa;
    float *p_gx, *p_lat3;
    int *p_perm, *p_tG, *p_tM0, *p_tE, *p_nG, *p_tT, *p_tM0a, *p_tEa, *p_nA;
    cudaGetSymbolAddress((void**)&p_fused, g_fused);
    cudaGetSymbolAddress((void**)&p_preW,  g_preW);
    cudaGetSymbolAddress((void**)&p_lat,   g_lat);
    cudaGetSymbolAddress((void**)&p_gx,    g_gx);
    cudaGetSymbolAddress((void**)&p_lat2,  g_lat2);
    cudaGetSymbolAddress((void**)&p_lat3,  g_lat3);
    cudaGetSymbolAddress((void**)&p_Wih,   g_Wih);
    cudaGetSymbolAddress((void**)&p_Wa,    g_Wa);
    cudaGetSymbolAddress((void**)&p_perm,  g_perm);
    cudaGetSymbolAddress((void**)&p_tG,    g_tileG);
    cudaGetSymbolAddress((void**)&p_tM0,   g_tileM0);
    cudaGetSymbolAddress((void**)&p_tE,    g_tileE);
    cudaGetSymbolAddress((void**)&p_nG,    g_nGru);
    cudaGetSymbolAddress((void**)&p_tT,    g_tileT);
    cudaGetSymbolAddress((void**)&p_tM0a,  g_tileM0a);
    cudaGetSymbolAddress((void**)&p_tEa,   g_tileEa);
    cudaGetSymbolAddress((void**)&p_nA,    g_nAd);

    // one-time resource creation (uncaptured correctness call creates them;
    // identical WORK is enqueued on every call)
    static cudaStream_t s_side = nullptr;
    static cudaEvent_t  s_e0 = nullptr, s_ew = nullptr, s_es = nullptr;
    if (s_side == nullptr) {
        cudaStreamCreateWithFlags(&s_side, cudaStreamNonBlocking);
        cudaEventCreateWithFlags(&s_e0, cudaEventDisableTiming);
        cudaEventCreateWithFlags(&s_ew, cudaEventDisableTiming);
        cudaEventCreateWithFlags(&s_es, cudaEventDisableTiming);
    }

    const int smem1 = 3 * (128 + 64)  * KS * 2;   // 46080
    const int smem2 = 3 * (128 + 128) * KS * 2;   // 61440
    cudaFuncSetAttribute(conv1_k, cudaFuncAttributeMaxDynamicSharedMemorySize, smem1);
    cudaFuncSetAttribute(conv2_k, cudaFuncAttributeMaxDynamicSharedMemorySize, smem2);
    cudaFuncSetAttribute(gemm_bf, cudaFuncAttributeMaxDynamicSharedMemorySize, smem2);

    // fork side stream off the main stream
    cudaEventRecord(s_e0, 0);
    cudaStreamWaitEvent(s_side, s_e0, 0);

    // side stream: conv weight re-layouts first (needed earliest)
    reorder_w1_k<<<216, 256, 0, s_side>>>(c1w);
    reorder_w2_k<<<288, 256, 0, s_side>>>(c2w);
    cudaEventRecord(s_ew, s_side);
    // then everything needed by pre/GRU/adapter
    reorder_pre_k<<<512, 256, 0, s_side>>>(prew);
    cvt_w_k<<<(N4_WIH + N4_WA + 255)/256, 256, 0, s_side>>>(W_ih, Wa);
    tail_k<<<768, 256, 0, s_side>>>(dir, task, ed, et);
    sort_count_k  <<<32, 256, 0, s_side>>>(task);
    sort_off_k    <<<1,  1,   0, s_side>>>();
    sort_scatter_k<<<32, 256, 0, s_side>>>(task);
    cudaEventRecord(s_es, s_side);

    // main stream: embedding gather (overlaps with side stream)
    embed_k<<<18816, 256>>>(obj, color, state, eo, ec, es);

    // join 1: conv weights ready
    cudaStreamWaitEvent(0, s_ew, 0);
    conv1_k<<<3136, 256, smem1>>>(c1b);
    conv2_k<<<3136, 256, smem2>>>(c2b);

    // join 2: preW, fused tail, sort ready
    cudaStreamWaitEvent(0, s_es, 0);

    // pre-linear: M=8192, N=512, K=6368, relu, bf16 out
    gemm_bf<<<dim3(64, 4), 256, smem2>>>(p_fused, FUSED, nullptr,
                                  p_preW, 0, preb, 0,
                                  nullptr, p_lat, HH, FUSED, 1, BB,
                                  nullptr, nullptr, nullptr, nullptr);

    // GRU gates: grouped (4 GRUs), perm gather; N=1536, K=512, f32 out
    gemm_bf<<<dim3(80, 12), 256, smem2>>>(p_lat, HH, p_perm,
                                   p_Wih, (long long)G3H*HH, b_ih, G3H,
                                   p_gx, nullptr, G3H, HH, 0, 0,
                                   p_tG, p_tM0, p_tE, p_nG);
    gru_elem_k<<<BB, 128>>>(b_hh);

    // adapter: grouped (8 tasks); N=512, K=512, relu, f32 out
    gemm_bf<<<dim3(80, 4), 256, smem2>>>(p_lat2, HH, nullptr,
                                  p_Wa, (long long)HH*HH, ba, HH,
                                  p_lat3, nullptr, HH, HH, 1, 0,
                                  p_tT, p_tM0a, p_tEa, p_nA);

    // policy heads + value
    heads_k<<<1024, 256>>>(Wh, bh2, vw, vb, out);
}